// round 7
// baseline (speedup 1.0000x reference)
#include <cuda_runtime.h>
#include <cstdint>

// Fixed shapes: B=2, C=128, D=H=W=16
#define NNODE 4096
#define CDIM  128
#define EDIM  46
#define BCNT  2
#define PROJW 256   // theta(64) | phi(64) | G2(128)  (r_w folded into G)
#define NB    444   // 3 blocks per SM exactly (148 SMs)
#define NT    256

// ---------------- scratch (device globals) ---------------------------------
__device__ float g_h[BCNT * NNODE * CDIM];
__device__ float g_proj[BCNT * NNODE * PROJW];
__device__ float g_f[BCNT * NNODE * EDIM];
__device__ float g_fp[NNODE * EDIM];
__device__ float g_fpn[NNODE * EDIM];
__device__ float g_pth[NNODE * 64];
__device__ float g_pph[NNODE * 64];
__device__ float g_ss[92 * 32];
__device__ float g_ssfp[46 * 32];
__device__ float g_Wcat[PROJW * CDIM];
__device__ float g_bcat[PROJW];
__device__ float g_y[3][BCNT * NNODE * CDIM];     // per-axis partials, 128-wide
__device__ int            g_cnt;
__device__ volatile int   g_sense;
__device__ int            g_ctr[16];              // work-stealing counters (zero-init)

// counter ids: 0=FP, 1+r=PROJ, 4+r=GRAM, 7+r=AGG
#define PH_FP    0
#define PH_PROJ(r) (1 + (r))
#define PH_GRAM(r) (4 + (r))
#define PH_AGG(r)  (7 + (r))

// ---------------- shared memory ---------------------------------------------
struct SmemProj { float Ah[32][72]; float Al[32][72]; float Bh[32][72]; float Bl[32][72]; };
struct SmemGram { float Th[16][68]; float Ph[16][68]; float ssl[46]; };
struct SmemAgg  { float Gs[16][132]; float fs[16][48]; float nrm2[92]; };
struct SmemTr   { float tile[32][33]; };
union __align__(16) Smem { SmemProj p; SmemGram r; SmemAgg a; SmemTr tr; };
__shared__ int s_next;

// ---------------- grid barrier (sense-reversing) ----------------------------
__device__ __forceinline__ void gsync() {
    __syncthreads();
    if (threadIdx.x == 0) {
        __threadfence();
        int s = g_sense;
        if (atomicAdd(&g_cnt, 1) == NB - 1) {
            g_cnt = 0;
            __threadfence();
            g_sense = s ^ 1;
        } else {
            while (g_sense == s) __nanosleep(32);
        }
        __threadfence();
    }
    __syncthreads();
}

// line decode: axis0 line=(j,k) step 256; axis1 line=(i,k) step 16; axis2 line=(i,j) step 1
__device__ __forceinline__ void line_decode(int axis, int line,
                                            int& nbase, int& step, int& c0, int& c1) {
    if (axis == 0)      { nbase = line; step = 256; c0 = 0; c1 = 0; }
    else if (axis == 1) { c0 = line >> 4; nbase = (c0 << 8) | (line & 15); step = 16; c1 = 0; }
    else                { c0 = line >> 4; c1 = line & 15; nbase = (c0 << 8) | (c1 << 4); step = 1; }
}
__device__ __forceinline__ int e_pos(int axis, int c0, int c1, int v, int vp) {
    if (axis == 0) return vp < v ? vp : vp + 30;
    if (axis == 1) return c0 + (vp < v ? vp : vp + 15);
    return c0 + c1 + vp;                          // includes self
}

// ---------------- 3xTF32 mma helper ------------------------------------------
__device__ __forceinline__ void mma8(float* c, const uint32_t* a, uint32_t b0, uint32_t b1) {
    asm volatile("mma.sync.aligned.m16n8k8.row.col.f32.tf32.tf32.f32 "
                 "{%0,%1,%2,%3},{%4,%5,%6,%7},{%8,%9},{%0,%1,%2,%3};\n"
                 : "+f"(c[0]), "+f"(c[1]), "+f"(c[2]), "+f"(c[3])
                 : "r"(a[0]), "r"(a[1]), "r"(a[2]), "r"(a[3]), "r"(b0), "r"(b1));
}

// ---------------- pipelined + work-stealing line-Gram phase ------------------
__device__ __forceinline__ void gram_phase(Smem& sm, int ph, int ntasks,
        const float* __restrict__ thA, const float* __restrict__ phA,
        int stride, int bStrideIn,
        float* __restrict__ fA, int fBStride,
        float* __restrict__ ssA, int ssBStride) {
    int t = threadIdx.x;
    int r = t >> 4, c = t & 15;
    if (t == 0) s_next = atomicAdd(&g_ctr[ph], 1);
    __syncthreads();
    int task = s_next;
    float4 tv, pv;
    int curNb = 0, curAxis = 0, curC0 = 0, curC1 = 0, curSt = 0, curB = 0;
    if (task < ntasks) {
        int b = task / 768, lt = task - b * 768;
        int axis = lt >> 8, line = lt & 255;
        int nb_, st, c0, c1; line_decode(axis, line, nb_, st, c0, c1);
        int n = nb_ + r * st;
        tv = *(const float4*)(thA + b * bStrideIn + n * stride + c * 4);
        pv = *(const float4*)(phA + b * bStrideIn + n * stride + c * 4);
        curNb = nb_; curAxis = axis; curC0 = c0; curC1 = c1; curSt = st; curB = b;
    }
    float* prevSs = nullptr;
    while (task < ntasks) {
        int nb_ = curNb, axis = curAxis, c0 = curC0, c1 = curC1, st = curSt, b = curB;
        if (t == 0) s_next = atomicAdd(&g_ctr[ph], 1);
        __syncthreads();                              // prev compute done; s_next visible
        if (t < 46 && prevSs) { float s = sm.r.ssl[t]; if (s != 0.f) atomicAdd(prevSs + t * 32, s); }
        *(float4*)&sm.r.Th[r][c * 4] = tv;
        *(float4*)&sm.r.Ph[r][c * 4] = pv;
        if (t < 46) sm.r.ssl[t] = 0.f;
        int next = s_next;
        if (next < ntasks) {                          // prefetch next task's tiles
            int b2 = next / 768, lt = next - b2 * 768;
            int axis2 = lt >> 8, line2 = lt & 255;
            int n2b, st2, c02, c12; line_decode(axis2, line2, n2b, st2, c02, c12);
            int n2 = n2b + r * st2;
            tv = *(const float4*)(thA + b2 * bStrideIn + n2 * stride + c * 4);
            pv = *(const float4*)(phA + b2 * bStrideIn + n2 * stride + c * 4);
            curNb = n2b; curAxis = axis2; curC0 = c02; curC1 = c12; curSt = st2; curB = b2;
        }
        __syncthreads();
        int v = r, vp = c;
        const float4* tr4 = (const float4*)&sm.r.Th[v][0];
        const float4* pr4 = (const float4*)&sm.r.Ph[vp][0];
        float acc = 0.f;
#pragma unroll
        for (int d = 0; d < 16; d++) {
            float4 a = tr4[d], p = pr4[d];
            acc += a.x * p.x + a.y * p.y + a.z * p.z + a.w * p.w;
        }
        if (axis == 2 || v != vp) {
            int e = e_pos(axis, c0, c1, v, vp);
            fA[b * fBStride + (nb_ + v * st) * EDIM + e] = acc;
            atomicAdd(&sm.r.ssl[e], acc * acc);
        }
        prevSs = ssA + b * ssBStride;
        task = next;
    }
    __syncthreads();
    if (t < 46 && prevSs) { float s = sm.r.ssl[t]; if (s != 0.f) atomicAdd(prevSs + t * 32, s); }
}

// ---------------- proj phase: 3xTF32 mma, 64x64 tiles, 512 tasks -------------
__device__ __forceinline__ void proj_phase(Smem& sm, int ph) {
    int t = threadIdx.x;
    int lane = t & 31, w = t >> 5;
    int g = lane >> 2, tg = lane & 3;
    int mrow = (w & 3) << 4;
    int nb = (w >> 2) << 5;
    for (;;) {
        if (t == 0) s_next = atomicAdd(&g_ctr[ph], 1);
        __syncthreads();
        int task = s_next;
        __syncthreads();
        if (task >= 512) break;
        int rowBase = (task >> 2) << 6, colBase = (task & 3) << 6;
        float acc[4][4];
#pragma unroll
        for (int i = 0; i < 4; i++)
#pragma unroll
            for (int j = 0; j < 4; j++) acc[i][j] = 0.f;

        for (int k0 = 0; k0 < 128; k0 += 32) {
            __syncthreads();
#pragma unroll
            for (int it = 0; it < 2; it++) {
                int idx = t + it * 256;
                int rr = idx & 63, k4 = idx >> 6;
                float4 va = *(const float4*)(g_h + (rowBase + rr) * 128 + k0 + k4 * 4);
                float4 vb = *(const float4*)(g_Wcat + (colBase + rr) * 128 + k0 + k4 * 4);
                const float* vaf = (const float*)&va;
                const float* vbf = (const float*)&vb;
#pragma unroll
                for (int jj = 0; jj < 4; jj++) {
                    float av = vaf[jj];
                    float ah = __uint_as_float(__float_as_uint(av) & 0xFFFFE000u);
                    sm.p.Ah[k4 * 4 + jj][rr] = ah;
                    sm.p.Al[k4 * 4 + jj][rr] = av - ah;
                    float bv = vbf[jj];
                    float bh = __uint_as_float(__float_as_uint(bv) & 0xFFFFE000u);
                    sm.p.Bh[k4 * 4 + jj][rr] = bh;
                    sm.p.Bl[k4 * 4 + jj][rr] = bv - bh;
                }
            }
            __syncthreads();
#pragma unroll
            for (int ks = 0; ks < 4; ks++) {
                int kr = ks * 8;
                uint32_t ah[4], al[4];
                ah[0] = __float_as_uint(sm.p.Ah[kr + tg][mrow + g]);
                ah[1] = __float_as_uint(sm.p.Ah[kr + tg][mrow + g + 8]);
                ah[2] = __float_as_uint(sm.p.Ah[kr + tg + 4][mrow + g]);
                ah[3] = __float_as_uint(sm.p.Ah[kr + tg + 4][mrow + g + 8]);
                al[0] = __float_as_uint(sm.p.Al[kr + tg][mrow + g]);
                al[1] = __float_as_uint(sm.p.Al[kr + tg][mrow + g + 8]);
                al[2] = __float_as_uint(sm.p.Al[kr + tg + 4][mrow + g]);
                al[3] = __float_as_uint(sm.p.Al[kr + tg + 4][mrow + g + 8]);
#pragma unroll
                for (int ch = 0; ch < 4; ch++) {
                    int nn = nb + ch * 8 + g;
                    uint32_t bh0 = __float_as_uint(sm.p.Bh[kr + tg][nn]);
                    uint32_t bh1 = __float_as_uint(sm.p.Bh[kr + tg + 4][nn]);
                    uint32_t bl0 = __float_as_uint(sm.p.Bl[kr + tg][nn]);
                    uint32_t bl1 = __float_as_uint(sm.p.Bl[kr + tg + 4][nn]);
                    mma8(acc[ch], ah, bh0, bh1);
                    mma8(acc[ch], ah, bl0, bl1);
                    mma8(acc[ch], al, bh0, bh1);
                }
            }
        }
#pragma unroll
        for (int ch = 0; ch < 4; ch++) {
            int col = colBase + nb + ch * 8 + 2 * tg;
            int row = rowBase + mrow + g;
            g_proj[row * PROJW + col]           = acc[ch][0] + g_bcat[col];
            g_proj[row * PROJW + col + 1]       = acc[ch][1] + g_bcat[col + 1];
            g_proj[(row + 8) * PROJW + col]     = acc[ch][2] + g_bcat[col];
            g_proj[(row + 8) * PROJW + col + 1] = acc[ch][3] + g_bcat[col + 1];
        }
    }
}

// ---------------- pipelined + stealing agg phase (128-wide G2) ---------------
__device__ __forceinline__ void agg_phase(Smem& sm, int ph) {
    int t = threadIdx.x;
    if (t < 92) sm.a.nrm2[t] = 1.f / (1e-6f + sqrtf(g_ss[t * 32]));
    int r = t >> 4, c = t & 15;
    if (t == 0) s_next = atomicAdd(&g_ctr[ph], 1);
    __syncthreads();
    int task = s_next;
    float4 gv0, gv1; float fv[3], qv[3]; int lnd[3], le[3];
#pragma unroll
    for (int ii = 0; ii < 3; ii++) {
        int l = t + ii * 256; lnd[ii] = l / 48; le[ii] = l - lnd[ii] * 48;
    }
    int curNb = 0, curAxis = 0, curC0 = 0, curC1 = 0, curSt = 0, curB = 0;
    if (task < 1536) {
        int b = task / 768, lt = task - b * 768;
        int axis = lt >> 8, line = lt & 255;
        int nb_, st, c0, c1; line_decode(axis, line, nb_, st, c0, c1);
        const float* gp = g_proj + (b * NNODE + nb_ + r * st) * PROJW + 128;
        gv0 = *(const float4*)(gp + c * 4);
        gv1 = *(const float4*)(gp + 64 + c * 4);
#pragma unroll
        for (int ii = 0; ii < 3; ii++) {
            if (le[ii] < 46) {
                int n = nb_ + lnd[ii] * st;
                fv[ii] = g_f[(b * NNODE + n) * EDIM + le[ii]];
                qv[ii] = g_fpn[n * EDIM + le[ii]];
            }
        }
        curNb = nb_; curAxis = axis; curC0 = c0; curC1 = c1; curSt = st; curB = b;
    }
    while (task < 1536) {
        int nb_ = curNb, axis = curAxis, c0 = curC0, c1 = curC1, st = curSt, b = curB;
        if (t == 0) s_next = atomicAdd(&g_ctr[ph], 1);
        __syncthreads();                    // prev compute done; s_next + nrm2 visible
        *(float4*)&sm.a.Gs[r][c * 4] = gv0;
        *(float4*)&sm.a.Gs[r][64 + c * 4] = gv1;
#pragma unroll
        for (int ii = 0; ii < 3; ii++)
            sm.a.fs[lnd[ii]][le[ii]] = (le[ii] < 46)
                ? fv[ii] * sm.a.nrm2[b * 46 + le[ii]] + qv[ii] : -1e30f;
        int next = s_next;
        if (next < 1536) {
            int b2 = next / 768, lt = next - b2 * 768;
            int axis2 = lt >> 8, line2 = lt & 255;
            int n2b, st2, c02, c12; line_decode(axis2, line2, n2b, st2, c02, c12);
            const float* gp = g_proj + (b2 * NNODE + n2b + r * st2) * PROJW + 128;
            gv0 = *(const float4*)(gp + c * 4);
            gv1 = *(const float4*)(gp + 64 + c * 4);
#pragma unroll
            for (int ii = 0; ii < 3; ii++) {
                if (le[ii] < 46) {
                    int n = n2b + lnd[ii] * st2;
                    fv[ii] = g_f[(b2 * NNODE + n) * EDIM + le[ii]];
                    qv[ii] = g_fpn[n * EDIM + le[ii]];
                }
            }
            curNb = n2b; curAxis = axis2; curC0 = c02; curC1 = c12; curSt = st2; curB = b2;
        }
        __syncthreads();
        int ty = r, tx = c;
        float a0 = sm.a.fs[ty][tx], a1 = sm.a.fs[ty][tx + 16], a2 = sm.a.fs[ty][tx + 32];
        float m = fmaxf(a0, fmaxf(a1, a2));
#pragma unroll
        for (int o = 8; o; o >>= 1) m = fmaxf(m, __shfl_xor_sync(0xffffffffu, m, o));
        float e0 = expf(a0 - m), e1 = expf(a1 - m), e2 = expf(a2 - m);
        float z = e0 + e1 + e2;
#pragma unroll
        for (int o = 8; o; o >>= 1) z += __shfl_xor_sync(0xffffffffu, z, o);
        float invZ = 1.f / z;
        sm.a.fs[ty][tx] = e0; sm.a.fs[ty][tx + 16] = e1; sm.a.fs[ty][tx + 32] = e2;
        __syncwarp();

        float4 acc0 = {0.f, 0.f, 0.f, 0.f}, acc1 = {0.f, 0.f, 0.f, 0.f};
#pragma unroll
        for (int vp = 0; vp < 16; vp++) {
            float w;
            if (axis == 2)      w = sm.a.fs[ty][c0 + c1 + vp];
            else if (vp == ty)  w = 0.f;
            else if (axis == 0) w = sm.a.fs[ty][vp < ty ? vp : vp + 30];
            else                w = sm.a.fs[ty][c0 + (vp < ty ? vp : vp + 15)];
            float4 ga = *(const float4*)&sm.a.Gs[vp][tx * 4];
            float4 gb = *(const float4*)&sm.a.Gs[vp][64 + tx * 4];
            acc0.x += w * ga.x; acc0.y += w * ga.y; acc0.z += w * ga.z; acc0.w += w * ga.w;
            acc1.x += w * gb.x; acc1.y += w * gb.y; acc1.z += w * gb.z; acc1.w += w * gb.w;
        }
        acc0.x *= invZ; acc0.y *= invZ; acc0.z *= invZ; acc0.w *= invZ;
        acc1.x *= invZ; acc1.y *= invZ; acc1.z *= invZ; acc1.w *= invZ;
        int n = nb_ + ty * st;
        float* yp = &g_y[axis][(b * NNODE + n) * CDIM];
        *(float4*)(yp + tx * 4) = acc0;
        *(float4*)(yp + 64 + tx * 4) = acc1;
        task = next;
    }
}

// ---------------- the single persistent kernel -------------------------------
__global__ __launch_bounds__(NT, 3) void k_all(
        const float* __restrict__ x,
        const float* __restrict__ Gw, const float* __restrict__ Gb,
        const float* __restrict__ thw, const float* __restrict__ thb,
        const float* __restrict__ phw, const float* __restrict__ phb,
        const float* __restrict__ rw, const float* __restrict__ rb,
        const float* __restrict__ gthw, const float* __restrict__ gthb,
        const float* __restrict__ gphw, const float* __restrict__ gphb,
        float* __restrict__ outp) {
    __shared__ Smem sm;
    const int t = threadIdx.x, bid = blockIdx.x;
    const int gtid = bid * NT + t, gs = NB * NT;
    const int AX = BCNT * NNODE * CDIM;

    // ---- phase PREP ----
    for (int task = bid; task < 1024; task += NB) {     // coalesced transpose tiles
        int b = task >> 9, ct = (task >> 7) & 3, nt = task & 127;
        __syncthreads();
        for (int l = t; l < 1024; l += NT) {
            int cc = l >> 5, nn = l & 31;
            sm.tr.tile[cc][nn] = x[(((b << 7) + (ct << 5) + cc) << 12) + (nt << 5) + nn];
        }
        __syncthreads();
        for (int l = t; l < 1024; l += NT) {
            int cc = l & 31, nn = l >> 5;
            g_h[(((b << 12) + (nt << 5) + nn) << 7) + (ct << 5) + cc] = sm.tr.tile[cc][nn];
        }
    }
    // theta/phi rows of Wcat
    for (int idx = gtid; idx < 128 * CDIM; idx += gs) {
        int r = idx >> 7, k = idx & 127;
        g_Wcat[idx] = (r < 64) ? thw[r * 128 + k] : phw[(r - 64) * 128 + k];
    }
    // W2 = r_w @ G_w  -> Wcat rows 128..255
    if (bid >= NB - 4) {
        int tile = bid - (NB - 4);
        int cc0 = (tile >> 1) << 6, kk0 = (tile & 1) << 6;
        for (int o = t; o < 4096; o += NT) {
            int cc = cc0 + (o >> 6), kk = kk0 + (o & 63);
            float s = 0.f;
            for (int gg = 0; gg < 64; gg++)
                s += rw[cc * 64 + gg] * Gw[gg * 128 + kk];
            g_Wcat[(128 + cc) * 128 + kk] = s;
        }
    }
    // bcat: thb | phb | (r_w@G_b + r_b)
    for (int idx = gtid; idx < PROJW; idx += gs) {
        if (idx < 64) g_bcat[idx] = thb[idx];
        else if (idx < 128) g_bcat[idx] = phb[idx - 64];
        else {
            int cc = idx - 128;
            float s = rb[cc];
            for (int gg = 0; gg < 64; gg++) s += rw[cc * 64 + gg] * Gb[gg];
            g_bcat[idx] = s;
        }
    }
    for (int idx = gtid; idx < 46; idx += gs) g_ssfp[idx * 32] = 0.f;
    for (int idx = gtid; idx < NNODE * 64; idx += gs) {
        int n = idx >> 6, d = idx & 63;
        int i = n >> 8, j = (n >> 4) & 15, k = n & 15;
        float p0 = i * (1.f / 15.f) - 0.5f;
        float p1 = j * (1.f / 15.f) - 0.5f;
        float p2 = k * (1.f / 15.f) - 0.5f;
        g_pth[idx] = p0 * gthw[d * 3] + p1 * gthw[d * 3 + 1] + p2 * gthw[d * 3 + 2] + gthb[d];
        g_pph[idx] = p0 * gphw[d * 3] + p1 * gphw[d * 3 + 1] + p2 * gphw[d * 3 + 2] + gphb[d];
    }
    gsync();

    // ---- phase FP: geo Gram lines (768 tasks) ----
    gram_phase(sm, PH_FP, 768, g_pth, g_pph, 64, 0, g_fp, 0, g_ssfp, 0);
    gsync();

    for (int r = 0; r < 3; r++) {
        // ---- phase P: projection GEMM (512 tasks) + zero g_ss (+fpn on r0) ----
        if (bid == 0 && t < 92) g_ss[t * 32] = 0.f;
        proj_phase(sm, PH_PROJ(r));
        if (r == 0) {
            for (int idx = gtid; idx < NNODE * EDIM; idx += gs) {
                int e = idx % EDIM;
                g_fpn[idx] = fmaxf(g_fp[idx] / (1e-6f + sqrtf(g_ssfp[e * 32])), 0.f);
            }
        }
        gsync();

        // ---- phase G: f Gram lines (1536 tasks) ----
        gram_phase(sm, PH_GRAM(r), 1536, g_proj, g_proj + 64, PROJW, NNODE * PROJW,
                   g_f, NNODE * EDIM, g_ss, EDIM * 32);
        gsync();

        // ---- phase A: softmax + 128-wide aggregate (1536 tasks) ----
        agg_phase(sm, PH_AGG(r));
        gsync();

        // ---- phase R: elementwise h += y0+y1+y2 (r_w folded into G) ----
        if (r == 2 && bid == 0 && t < 16) g_ctr[t] = 0;   // reset steal counters for replay
        for (int i4 = gtid; i4 < AX / 4; i4 += gs) {
            const float* yb = &g_y[0][i4 * 4];
            float4 h4 = *(const float4*)&g_h[i4 * 4];
            float4 v0 = *(const float4*)yb;
            float4 v1 = *(const float4*)(yb + AX);
            float4 v2 = *(const float4*)(yb + 2 * AX);
            float4 val;
            val.x = h4.x + v0.x + v1.x + v2.x;
            val.y = h4.y + v0.y + v1.y + v2.y;
            val.z = h4.z + v0.z + v1.z + v2.z;
            val.w = h4.w + v0.w + v1.w + v2.w;
            if (r == 2) {                                  // scatter to out [B,C,N]
                int elem = i4 * 4;
                int b = elem >> 19, rem = elem & ((1 << 19) - 1);
                int n = rem >> 7, c = rem & 127;
                outp[(((b << 7) + c) << 12) + n]     = val.x;
                outp[(((b << 7) + c + 1) << 12) + n] = val.y;
                outp[(((b << 7) + c + 2) << 12) + n] = val.z;
                outp[(((b << 7) + c + 3) << 12) + n] = val.w;
            } else {
                *(float4*)&g_h[i4 * 4] = val;
            }
        }
        if (r < 2) gsync();
    }
}

// ---------------------------------------------------------------------------
extern "C" void kernel_launch(void* const* d_in, const int* in_sizes, int n_in,
                              void* d_out, int out_size) {
    const float* x    = (const float*)d_in[0];
    const float* G_w  = (const float*)d_in[1];
    const float* G_b  = (const float*)d_in[2];
    const float* th_w = (const float*)d_in[3];
    const float* th_b = (const float*)d_in[4];
    const float* ph_w = (const float*)d_in[5];
    const float* ph_b = (const float*)d_in[6];
    const float* r_w  = (const float*)d_in[7];
    const float* r_b  = (const float*)d_in[8];
    const float* gt_w = (const float*)d_in[9];
    const float* gt_b = (const float*)d_in[10];
    const float* gp_w = (const float*)d_in[11];
    const float* gp_b = (const float*)d_in[12];
    float* out = (float*)d_out;

    k_all<<<NB, NT>>>(x, G_w, G_b, th_w, th_b, ph_w, ph_b, r_w, r_b,
                      gt_w, gt_b, gp_w, gp_b, out);
}

// round 8
// speedup vs baseline: 1.0150x; 1.0150x over previous
#include <cuda_runtime.h>
#include <cstdint>

// Fixed shapes: B=2, C=128, D=H=W=16
#define NNODE 4096
#define CDIM  128
#define EDIM  46
#define BCNT  2
#define PROJW 192   // theta(64) | phi(64) | G(64)
#define NB    512
#define NT    256
#define NGRP  64    // barrier groups (8 blocks each)

// ---------------- scratch (device globals) ---------------------------------
__device__ float g_h[BCNT * NNODE * CDIM];
__device__ float g_proj[BCNT * NNODE * PROJW];
__device__ float g_f[BCNT * NNODE * EDIM];
__device__ float g_fp[NNODE * EDIM];
__device__ float g_fpn[NNODE * EDIM];             // relu(l2norm(f_p)) precomputed
__device__ float g_pth[NNODE * 64];
__device__ float g_pph[NNODE * 64];
__device__ float g_ss[92 * 32];
__device__ float g_ssfp[46 * 32];
__device__ float g_Wcat[PROJW * CDIM];
__device__ float g_bcat[PROJW];
__device__ float g_y[3][BCNT * NNODE * 64];
__device__ int            g_cnt1[NGRP * 32];      // padded group counters (128B apart)
__device__ int            g_cnt2;                 // root counter
__device__ volatile int   g_sense;

// ---------------- shared memory union ---------------------------------------
struct SmemProj { float Ah[32][72]; float Al[32][72]; float Bh[32][72]; float Bl[32][72]; }; // 36864B
struct SmemGemm { float A[32][68]; float B[32][68]; };
struct SmemGram { float Th[16][68]; float Ph[16][68]; float ssl[46]; };
struct SmemAgg  { float Gs[16][68]; float fs[16][48]; float nrm2[92]; };
struct SmemTr   { float tile[32][33]; };
union __align__(16) Smem { SmemProj p; SmemGemm g; SmemGram r; SmemAgg a; SmemTr tr; };

// ---------------- hierarchical grid barrier (2-level, sense-reversing) -------
// Level 1: 8 blocks arrive at their group counter (contention 8).
// Level 2: 64 group-lasts arrive at root (contention 64). Root flips sense.
__device__ __forceinline__ void gsync() {
    __syncthreads();
    if (threadIdx.x == 0) {
        __threadfence();
        int s = g_sense;
        int grp = blockIdx.x & (NGRP - 1);
        if (atomicAdd(&g_cnt1[grp * 32], 1) == (NB / NGRP) - 1) {
            g_cnt1[grp * 32] = 0;                 // reset before root arrive
            __threadfence();
            if (atomicAdd(&g_cnt2, 1) == NGRP - 1) {
                g_cnt2 = 0;
                __threadfence();
                g_sense = s ^ 1;
            } else {
                while (g_sense == s) __nanosleep(32);
            }
        } else {
            while (g_sense == s) __nanosleep(32);
        }
        __threadfence();
    }
    __syncthreads();
}

// line decode: axis0 line=(j,k) step 256; axis1 line=(i,k) step 16; axis2 line=(i,j) step 1
__device__ __forceinline__ void line_decode(int axis, int line,
                                            int& nbase, int& step, int& c0, int& c1) {
    if (axis == 0)      { nbase = line; step = 256; c0 = 0; c1 = 0; }
    else if (axis == 1) { c0 = line >> 4; nbase = (c0 << 8) | (line & 15); step = 16; c1 = 0; }
    else                { c0 = line >> 4; c1 = line & 15; nbase = (c0 << 8) | (c1 << 4); step = 1; }
}
__device__ __forceinline__ int e_pos(int axis, int c0, int c1, int v, int vp) {
    if (axis == 0) return vp < v ? vp : vp + 30;
    if (axis == 1) return c0 + (vp < v ? vp : vp + 15);
    return c0 + c1 + vp;                          // includes self
}

// ---------------- 3xTF32 mma helper ------------------------------------------
__device__ __forceinline__ void mma8(float* c, const uint32_t* a, uint32_t b0, uint32_t b1) {
    asm volatile("mma.sync.aligned.m16n8k8.row.col.f32.tf32.tf32.f32 "
                 "{%0,%1,%2,%3},{%4,%5,%6,%7},{%8,%9},{%0,%1,%2,%3};\n"
                 : "+f"(c[0]), "+f"(c[1]), "+f"(c[2]), "+f"(c[3])
                 : "r"(a[0]), "r"(a[1]), "r"(a[2]), "r"(a[3]), "r"(b0), "r"(b1));
}

// ---------------- pipelined line-Gram phase ----------------------------------
__device__ __forceinline__ void gram_phase(Smem& sm, int bid, int ntasks,
        const float* __restrict__ thA, const float* __restrict__ phA,
        int stride, int bStrideIn,
        float* __restrict__ fA, int fBStride,
        float* __restrict__ ssA, int ssBStride) {
    int t = threadIdx.x;
    int r = t >> 4, c = t & 15;
    int task = bid;
    bool have = task < ntasks;
    float4 tv, pv;
    int curNb = 0, curAxis = 0, curC0 = 0, curC1 = 0, curSt = 0, curB = 0;
    if (have) {
        int b = task / 768, lt = task - b * 768;
        int axis = lt >> 8, line = lt & 255;
        int nb_, st, c0, c1; line_decode(axis, line, nb_, st, c0, c1);
        int n = nb_ + r * st;
        tv = *(const float4*)(thA + b * bStrideIn + n * stride + c * 4);
        pv = *(const float4*)(phA + b * bStrideIn + n * stride + c * 4);
        curNb = nb_; curAxis = axis; curC0 = c0; curC1 = c1; curSt = st; curB = b;
    }
    float* prevSs = nullptr;
    while (have) {
        int nb_ = curNb, axis = curAxis, c0 = curC0, c1 = curC1, st = curSt, b = curB;
        __syncthreads();                              // prev compute done
        if (t < 46 && prevSs) { float s = sm.r.ssl[t]; if (s != 0.f) atomicAdd(prevSs + t * 32, s); }
        *(float4*)&sm.r.Th[r][c * 4] = tv;
        *(float4*)&sm.r.Ph[r][c * 4] = pv;
        if (t < 46) sm.r.ssl[t] = 0.f;
        task += NB; have = task < ntasks;
        if (have) {                                   // prefetch next (overlaps compute)
            int b2 = task / 768, lt = task - b2 * 768;
            int axis2 = lt >> 8, line2 = lt & 255;
            int n2b, st2, c02, c12; line_decode(axis2, line2, n2b, st2, c02, c12);
            int n2 = n2b + r * st2;
            tv = *(const float4*)(thA + b2 * bStrideIn + n2 * stride + c * 4);
            pv = *(const float4*)(phA + b2 * bStrideIn + n2 * stride + c * 4);
            curNb = n2b; curAxis = axis2; curC0 = c02; curC1 = c12; curSt = st2; curB = b2;
        }
        __syncthreads();
        int v = r, vp = c;
        const float4* tr4 = (const float4*)&sm.r.Th[v][0];
        const float4* pr4 = (const float4*)&sm.r.Ph[vp][0];
        float acc = 0.f;
#pragma unroll
        for (int d = 0; d < 16; d++) {
            float4 a = tr4[d], p = pr4[d];
            acc += a.x * p.x + a.y * p.y + a.z * p.z + a.w * p.w;
        }
        if (axis == 2 || v != vp) {
            int e = e_pos(axis, c0, c1, v, vp);
            fA[b * fBStride + (nb_ + v * st) * EDIM + e] = acc;
            atomicAdd(&sm.r.ssl[e], acc * acc);
        }
        prevSs = ssA + b * ssBStride;
    }
    __syncthreads();
    if (t < 46 && prevSs) { float s = sm.r.ssl[t]; if (s != 0.f) atomicAdd(prevSs + t * 32, s); }
}

// ---------------- proj phase: 3xTF32 mma, 64x64 tiles ------------------------
__device__ __forceinline__ void proj_phase(Smem& sm, int bid) {
    int t = threadIdx.x;
    int lane = t & 31, w = t >> 5;
    int g = lane >> 2, tg = lane & 3;
    int mrow = (w & 3) << 4;          // warp m-offset within 64
    int nb = (w >> 2) << 5;           // warp n-offset within 64
    for (int task = bid; task < 384; task += NB) {
        int rowTile = task / 3;
        int rowBase = rowTile << 6, colBase = (task - rowTile * 3) << 6;
        float acc[4][4];
#pragma unroll
        for (int i = 0; i < 4; i++)
#pragma unroll
            for (int j = 0; j < 4; j++) acc[i][j] = 0.f;

        for (int k0 = 0; k0 < 128; k0 += 32) {
            __syncthreads();
#pragma unroll
            for (int it = 0; it < 2; it++) {
                int idx = t + it * 256;
                int rr = idx & 63, k4 = idx >> 6;
                float4 va = *(const float4*)(g_h + (rowBase + rr) * 128 + k0 + k4 * 4);
                float4 vb = *(const float4*)(g_Wcat + (colBase + rr) * 128 + k0 + k4 * 4);
                const float* vaf = (const float*)&va;
                const float* vbf = (const float*)&vb;
#pragma unroll
                for (int jj = 0; jj < 4; jj++) {
                    float av = vaf[jj];
                    float ah = __uint_as_float(__float_as_uint(av) & 0xFFFFE000u);
                    sm.p.Ah[k4 * 4 + jj][rr] = ah;
                    sm.p.Al[k4 * 4 + jj][rr] = av - ah;
                    float bv = vbf[jj];
                    float bh = __uint_as_float(__float_as_uint(bv) & 0xFFFFE000u);
                    sm.p.Bh[k4 * 4 + jj][rr] = bh;
                    sm.p.Bl[k4 * 4 + jj][rr] = bv - bh;
                }
            }
            __syncthreads();
#pragma unroll
            for (int ks = 0; ks < 4; ks++) {
                int kr = ks * 8;
                uint32_t ah[4], al[4];
                ah[0] = __float_as_uint(sm.p.Ah[kr + tg][mrow + g]);
                ah[1] = __float_as_uint(sm.p.Ah[kr + tg][mrow + g + 8]);
                ah[2] = __float_as_uint(sm.p.Ah[kr + tg + 4][mrow + g]);
                ah[3] = __float_as_uint(sm.p.Ah[kr + tg + 4][mrow + g + 8]);
                al[0] = __float_as_uint(sm.p.Al[kr + tg][mrow + g]);
                al[1] = __float_as_uint(sm.p.Al[kr + tg][mrow + g + 8]);
                al[2] = __float_as_uint(sm.p.Al[kr + tg + 4][mrow + g]);
                al[3] = __float_as_uint(sm.p.Al[kr + tg + 4][mrow + g + 8]);
#pragma unroll
                for (int ch = 0; ch < 4; ch++) {
                    int nn = nb + ch * 8 + g;
                    uint32_t bh0 = __float_as_uint(sm.p.Bh[kr + tg][nn]);
                    uint32_t bh1 = __float_as_uint(sm.p.Bh[kr + tg + 4][nn]);
                    uint32_t bl0 = __float_as_uint(sm.p.Bl[kr + tg][nn]);
                    uint32_t bl1 = __float_as_uint(sm.p.Bl[kr + tg + 4][nn]);
                    mma8(acc[ch], ah, bh0, bh1);     // hi*hi
                    mma8(acc[ch], ah, bl0, bl1);     // hi*lo
                    mma8(acc[ch], al, bh0, bh1);     // lo*hi
                }
            }
        }
#pragma unroll
        for (int ch = 0; ch < 4; ch++) {
            int col = colBase + nb + ch * 8 + 2 * tg;
            int row = rowBase + mrow + g;
            g_proj[row * PROJW + col]         = acc[ch][0] + g_bcat[col];
            g_proj[row * PROJW + col + 1]     = acc[ch][1] + g_bcat[col + 1];
            g_proj[(row + 8) * PROJW + col]     = acc[ch][2] + g_bcat[col];
            g_proj[(row + 8) * PROJW + col + 1] = acc[ch][3] + g_bcat[col + 1];
        }
    }
}

// ---------------- pipelined agg phase ----------------------------------------
__device__ __forceinline__ void agg_phase(Smem& sm, int bid) {
    int t = threadIdx.x;
    if (t < 92) sm.a.nrm2[t] = 1.f / (1e-6f + sqrtf(g_ss[t * 32]));  // both batches
    int r = t >> 4, c = t & 15;
    int task = bid;                         // 1536 tasks: exactly 3 per block
    float4 gv; float fv[3], qv[3]; int lnd[3], le[3];
    int curNb, curAxis, curC0, curC1, curSt, curB;
    {
        int b = task / 768, lt = task - b * 768;
        int axis = lt >> 8, line = lt & 255;
        int nb_, st, c0, c1; line_decode(axis, line, nb_, st, c0, c1);
        gv = *(const float4*)(g_proj + (b * NNODE + nb_ + r * st) * PROJW + 128 + c * 4);
#pragma unroll
        for (int ii = 0; ii < 3; ii++) {
            int l = t + ii * 256; int nd = l / 48, e = l - nd * 48;
            lnd[ii] = nd; le[ii] = e;
            if (e < 46) {
                int n = nb_ + nd * st;
                fv[ii] = g_f[(b * NNODE + n) * EDIM + e];
                qv[ii] = g_fpn[n * EDIM + e];
            }
        }
        curNb = nb_; curAxis = axis; curC0 = c0; curC1 = c1; curSt = st; curB = b;
    }
    bool have = true;
    while (have) {
        int nb_ = curNb, axis = curAxis, c0 = curC0, c1 = curC1, st = curSt, b = curB;
        __syncthreads();                    // prev compute done; nrm2 visible
        *(float4*)&sm.a.Gs[r][c * 4] = gv;
#pragma unroll
        for (int ii = 0; ii < 3; ii++)
            sm.a.fs[lnd[ii]][le[ii]] = (le[ii] < 46)
                ? fv[ii] * sm.a.nrm2[b * 46 + le[ii]] + qv[ii] : -1e30f;
        task += NB; have = task < 1536;
        if (have) {                         // prefetch next
            int b2 = task / 768, lt = task - b2 * 768;
            int axis2 = lt >> 8, line2 = lt & 255;
            int n2b, st2, c02, c12; line_decode(axis2, line2, n2b, st2, c02, c12);
            gv = *(const float4*)(g_proj + (b2 * NNODE + n2b + r * st2) * PROJW + 128 + c * 4);
#pragma unroll
            for (int ii = 0; ii < 3; ii++) {
                if (le[ii] < 46) {
                    int n = n2b + lnd[ii] * st2;
                    fv[ii] = g_f[(b2 * NNODE + n) * EDIM + le[ii]];
                    qv[ii] = g_fpn[n * EDIM + le[ii]];
                }
            }
            curNb = n2b; curAxis = axis2; curC0 = c02; curC1 = c12; curSt = st2; curB = b2;
        }
        __syncthreads();
        int ty = r, tx = c;
        float a0 = sm.a.fs[ty][tx], a1 = sm.a.fs[ty][tx + 16], a2 = sm.a.fs[ty][tx + 32];
        float m = fmaxf(a0, fmaxf(a1, a2));
#pragma unroll
        for (int o = 8; o; o >>= 1) m = fmaxf(m, __shfl_xor_sync(0xffffffffu, m, o));
        float e0 = expf(a0 - m), e1 = expf(a1 - m), e2 = expf(a2 - m);
        float z = e0 + e1 + e2;
#pragma unroll
        for (int o = 8; o; o >>= 1) z += __shfl_xor_sync(0xffffffffu, z, o);
        float invZ = 1.f / z;
        sm.a.fs[ty][tx] = e0; sm.a.fs[ty][tx + 16] = e1; sm.a.fs[ty][tx + 32] = e2;
        __syncwarp();

        float4 acc = {0.f, 0.f, 0.f, 0.f};
#pragma unroll
        for (int vp = 0; vp < 16; vp++) {
            float w;
            if (axis == 2)      w = sm.a.fs[ty][c0 + c1 + vp];
            else if (vp == ty)  w = 0.f;
            else if (axis == 0) w = sm.a.fs[ty][vp < ty ? vp : vp + 30];
            else                w = sm.a.fs[ty][c0 + (vp < ty ? vp : vp + 15)];
            float4 gg = *(const float4*)&sm.a.Gs[vp][tx * 4];
            acc.x += w * gg.x; acc.y += w * gg.y; acc.z += w * gg.z; acc.w += w * gg.w;
        }
        acc.x *= invZ; acc.y *= invZ; acc.z *= invZ; acc.w *= invZ;
        int n = nb_ + ty * st;
        *(float4*)&g_y[axis][(b * NNODE + n) * 64 + tx * 4] = acc;
    }
}

// ---------------- resid GEMM tile (scalar FFMA; small) -----------------------
__device__ __forceinline__ void resid_tile(Smem& sm, int task,
        const float* __restrict__ rw, const float* __restrict__ rb,
        float* __restrict__ outp, int last) {
    int rowBase = (task >> 1) << 6, colBase = (task & 1) << 6;
    int t = threadIdx.x, tx = t & 15, ty = t >> 4;
    const int AX = BCNT * NNODE * 64;
    float acc[4][4] = {};
    for (int k0 = 0; k0 < 64; k0 += 32) {
#pragma unroll
        for (int it = 0; it < 2; it++) {
            int idx = t + it * 256;
            int r = idx & 63, k4 = idx >> 6;
            const float* yb = &g_y[0][(rowBase + r) * 64 + k0 + k4 * 4];
            float4 v0 = *(const float4*)yb;
            float4 v1 = *(const float4*)(yb + AX);
            float4 v2 = *(const float4*)(yb + 2 * AX);
            sm.g.A[k4 * 4 + 0][r] = v0.x + v1.x + v2.x;
            sm.g.A[k4 * 4 + 1][r] = v0.y + v1.y + v2.y;
            sm.g.A[k4 * 4 + 2][r] = v0.z + v1.z + v2.z;
            sm.g.A[k4 * 4 + 3][r] = v0.w + v1.w + v2.w;
            float4 w = *(const float4*)(rw + (colBase + r) * 64 + k0 + k4 * 4);
            sm.g.B[k4 * 4 + 0][r] = w.x; sm.g.B[k4 * 4 + 1][r] = w.y;
            sm.g.B[k4 * 4 + 2][r] = w.z; sm.g.B[k4 * 4 + 3][r] = w.w;
        }
        __syncthreads();
#pragma unroll
        for (int kk = 0; kk < 32; kk++) {
            float4 a = *(const float4*)&sm.g.A[kk][ty * 4];
            float4 b = *(const float4*)&sm.g.B[kk][tx * 4];
            float av[4] = {a.x, a.y, a.z, a.w};
            float bv[4] = {b.x, b.y, b.z, b.w};
#pragma unroll
            for (int i = 0; i < 4; i++)
#pragma unroll
                for (int j = 0; j < 4; j++) acc[i][j] += av[i] * bv[j];
        }
        __syncthreads();
    }
#pragma unroll
    for (int i = 0; i < 4; i++) {
        int row = rowBase + ty * 4 + i;
#pragma unroll
        for (int j = 0; j < 4; j++) {
            int c = colBase + tx * 4 + j;
            float val = acc[i][j] + rb[c] + g_h[row * 128 + c];
            if (last) {
                int b = row >> 12, n = row & 4095;
                outp[(((b << 7) + c) << 12) + n] = val;
            } else {
                g_h[row * 128 + c] = val;
            }
        }
    }
}

// ---------------- the single persistent kernel -------------------------------
__global__ __launch_bounds__(NT, 4) void k_all(
        const float* __restrict__ x,
        const float* __restrict__ Gw, const float* __restrict__ Gb,
        const float* __restrict__ thw, const float* __restrict__ thb,
        const float* __restrict__ phw, const float* __restrict__ phb,
        const float* __restrict__ rw, const float* __restrict__ rb,
        const float* __restrict__ gthw, const float* __restrict__ gthb,
        const float* __restrict__ gphw, const float* __restrict__ gphb,
        float* __restrict__ outp) {
    __shared__ Smem sm;
    const int t = threadIdx.x, bid = blockIdx.x;
    const int gtid = bid * NT + t, gs = NB * NT;

    // ---- phase PREP ----
    // coalesced transpose via 32x32 smem tiles: 1024 tiles
    for (int task = bid; task < 1024; task += NB) {
        int b = task >> 9, ct = (task >> 7) & 3, nt = task & 127;
        __syncthreads();
        for (int l = t; l < 1024; l += NT) {
            int cc = l >> 5, nn = l & 31;
            sm.tr.tile[cc][nn] = x[(((b << 7) + (ct << 5) + cc) << 12) + (nt << 5) + nn];
        }
        __syncthreads();
        for (int l = t; l < 1024; l += NT) {
            int cc = l & 31, nn = l >> 5;
            g_h[(((b << 12) + (nt << 5) + nn) << 7) + (ct << 5) + cc] = sm.tr.tile[cc][nn];
        }
    }
    for (int idx = gtid; idx < PROJW * CDIM; idx += gs) {
        int r = idx >> 7, k = idx & 127;
        g_Wcat[idx] = (r < 64) ? thw[r * 128 + k]
                    : (r < 128) ? phw[(r - 64) * 128 + k]
                    : Gw[(r - 128) * 128 + k];
    }
    for (int idx = gtid; idx < PROJW; idx += gs)
        g_bcat[idx] = (idx < 64) ? thb[idx] : (idx < 128) ? phb[idx - 64] : Gb[idx - 128];
    for (int idx = gtid; idx < 46; idx += gs) g_ssfp[idx * 32] = 0.f;
    for (int idx = gtid; idx < NNODE * 64; idx += gs) {
        int n = idx >> 6, d = idx & 63;
        int i = n >> 8, j = (n >> 4) & 15, k = n & 15;
        float p0 = i * (1.f / 15.f) - 0.5f;
        float p1 = j * (1.f / 15.f) - 0.5f;
        float p2 = k * (1.f / 15.f) - 0.5f;
        g_pth[idx] = p0 * gthw[d * 3] + p1 * gthw[d * 3 + 1] + p2 * gthw[d * 3 + 2] + gthb[d];
        g_pph[idx] = p0 * gphw[d * 3] + p1 * gphw[d * 3 + 1] + p2 * gphw[d * 3 + 2] + gphb[d];
    }
    gsync();

    // ---- phase FP: geo Gram lines ----
    gram_phase(sm, bid, 768, g_pth, g_pph, 64, 0, g_fp, 0, g_ssfp, 0);
    gsync();

    for (int r = 0; r < 3; r++) {
        // ---- phase P: projection GEMM (3xTF32 mma) + zero g_ss (+FPN on r0) ----
        if (bid == 0 && t < 92) g_ss[t * 32] = 0.f;
        proj_phase(sm, bid);
        if (r == 0) {
            // normalized relu'd f_p (reads g_fp/g_ssfp finalized before prev gsync)
            for (int idx = gtid; idx < NNODE * EDIM; idx += gs) {
                int e = idx % EDIM;
                g_fpn[idx] = fmaxf(g_fp[idx] / (1e-6f + sqrtf(g_ssfp[e * 32])), 0.f);
            }
        }
        gsync();

        // ---- phase G: f Gram lines ----
        gram_phase(sm, bid, 1536, g_proj, g_proj + 64, PROJW, NNODE * PROJW,
                   g_f, NNODE * EDIM, g_ss, EDIM * 32);
        gsync();

        // ---- phase A: softmax + aggregate ----
        agg_phase(sm, bid);
        gsync();

        // ---- phase R: residual GEMM ----
        for (int task = bid; task < 256; task += NB)
            resid_tile(sm, task, rw, rb, outp, r == 2);
        if (r < 2) gsync();
    }
}

// ---------------------------------------------------------------------------
extern "C" void kernel_launch(void* const* d_in, const int* in_sizes, int n_in,
                              void* d_out, int out_size) {
    const float* x    = (const float*)d_in[0];
    const float* G_w  = (const float*)d_in[1];
    const float* G_b  = (const float*)d_in[2];
    const float* th_w = (const float*)d_in[3];
    const float* th_b = (const float*)d_in[4];
    const float* ph_w = (const float*)d_in[5];
    const float* ph_b = (const float*)d_in[6];
    const float* r_w  = (const float*)d_in[7];
    const float* r_b  = (const float*)d_in[8];
    const float* gt_w = (const float*)d_in[9];
    const float* gt_b = (const float*)d_in[10];
    const float* gp_w = (const float*)d_in[11];
    const float* gp_b = (const float*)d_in[12];
    float* out = (float*)d_out;

    k_all<<<NB, NT>>>(x, G_w, G_b, th_w, th_b, ph_w, ph_b, r_w, r_b,
                      gt_w, gt_b, gp_w, gp_b, out);
}

// round 9
// speedup vs baseline: 1.0990x; 1.0827x over previous
#include <cuda_runtime.h>
#include <cstdint>

// Fixed shapes: B=2, C=128, D=H=W=16
#define NNODE 4096
#define CDIM  128
#define EDIM  46
#define BCNT  2
#define PROJW 192   // theta(64) | phi(64) | G(64)
#define NB    512
#define NT    256

// ---------------- scratch (device globals) ---------------------------------
__device__ float g_h[BCNT * NNODE * CDIM];
__device__ float g_proj[BCNT * NNODE * PROJW];
__device__ float g_f[BCNT * NNODE * EDIM];
__device__ float g_fp[NNODE * EDIM];
__device__ float g_fpn[NNODE * EDIM];             // relu(l2norm(f_p)) precomputed
__device__ float g_pth[NNODE * 64];
__device__ float g_pph[NNODE * 64];
__device__ float g_ss[92 * 32];
__device__ float g_ssfp[46 * 32];
__device__ float g_Wcat[PROJW * CDIM];
__device__ float g_bcat[PROJW];
__device__ float g_y[3][BCNT * NNODE * 64];
__device__ int            g_cnt;
__device__ volatile int   g_sense;

// ---------------- shared memory union ---------------------------------------
struct SmemProj { float Ah[32][72]; float Al[32][72]; float Bh[32][72]; float Bl[32][72]; }; // 36864B
struct SmemGemm { float A[32][68]; float B[32][68]; };
struct SmemGram4 { float T[4][2][16][68]; float ssl[4][48]; };   // 4 lines x (Th,Ph)
struct SmemAgg  { float Gs[16][68]; float fs[16][48]; float nrm2[92]; };
struct SmemTr   { float tile[32][33]; };
union __align__(16) Smem { SmemProj p; SmemGemm g; SmemGram4 r4; SmemAgg a; SmemTr tr; };

// ---------------- flat grid barrier (sense-reversing) ------------------------
__device__ __forceinline__ void gsync() {
    __syncthreads();
    if (threadIdx.x == 0) {
        __threadfence();
        int s = g_sense;
        if (atomicAdd(&g_cnt, 1) == NB - 1) {
            g_cnt = 0;
            __threadfence();
            g_sense = s ^ 1;
        } else {
            while (g_sense == s) __nanosleep(32);
        }
        __threadfence();
    }
    __syncthreads();
}

// line decode: axis0 line=(j,k) step 256; axis1 line=(i,k) step 16; axis2 line=(i,j) step 1
__device__ __forceinline__ void line_decode(int axis, int line,
                                            int& nbase, int& step, int& c0, int& c1) {
    if (axis == 0)      { nbase = line; step = 256; c0 = 0; c1 = 0; }
    else if (axis == 1) { c0 = line >> 4; nbase = (c0 << 8) | (line & 15); step = 16; c1 = 0; }
    else                { c0 = line >> 4; c1 = line & 15; nbase = (c0 << 8) | (c1 << 4); step = 1; }
}
__device__ __forceinline__ int e_pos(int axis, int c0, int c1, int v, int vp) {
    if (axis == 0) return vp < v ? vp : vp + 30;
    if (axis == 1) return c0 + (vp < v ? vp : vp + 15);
    return c0 + c1 + vp;                          // includes self
}

// ---------------- 3xTF32 mma helper ------------------------------------------
__device__ __forceinline__ void mma8(float* c, const uint32_t* a, uint32_t b0, uint32_t b1) {
    asm volatile("mma.sync.aligned.m16n8k8.row.col.f32.tf32.tf32.f32 "
                 "{%0,%1,%2,%3},{%4,%5,%6,%7},{%8,%9},{%0,%1,%2,%3};\n"
                 : "+f"(c[0]), "+f"(c[1]), "+f"(c[2]), "+f"(c[3])
                 : "r"(a[0]), "r"(a[1]), "r"(a[2]), "r"(a[3]), "r"(b0), "r"(b1));
}

// ---------------- gram: 4 lines per block, 2x2 register tiling ---------------
// One task per block. 64 threads per line; thread (v2,vp2) computes the 2x2
// sub-block D[2v2..+1][2vp2..+1] of the 16x16 line Gram.
__device__ __forceinline__ void gram4(Smem& sm, int task,
        const float* __restrict__ thA, const float* __restrict__ phA,
        int stride, int bStrideIn,
        float* __restrict__ fOut, int fBStride,
        float* __restrict__ ssOut, int ssBStride) {
    int t = threadIdx.x;
    int L0 = task << 2;
    int b = L0 / 768, lt = L0 - b * 768;
    int axis = lt >> 8, lineBase = lt & 255;     // groups of 4 never cross axis/batch
    const float* thB = thA + b * bStrideIn;
    const float* phB = phA + b * bStrideIn;

    if (t < 192) (&sm.r4.ssl[0][0])[t] = 0.f;

    // cooperative load: 4 lines x 2 tiles x 16 rows x 64 floats; 8x LDG.128/thread
#pragma unroll
    for (int i = 0; i < 8; i++) {
        int c = t + (i << 8);
        int tile = c >> 8;                        // 0..7
        int g = tile >> 1, which = tile & 1;
        int r = (c >> 4) & 15, off = c & 15;
        int nbse, st, c0, c1; line_decode(axis, lineBase + g, nbse, st, c0, c1);
        const float* src = (which ? phB : thB) + (nbse + r * st) * stride + off * 4;
        *(float4*)&sm.r4.T[g][which][r][off * 4] = *(const float4*)src;
    }
    __syncthreads();

    int g = t >> 6, s = t & 63;
    int v2 = s >> 3, vp2 = s & 7;
    int nbse, st, c0, c1; line_decode(axis, lineBase + g, nbse, st, c0, c1);
    const float4* t0 = (const float4*)&sm.r4.T[g][0][2 * v2][0];
    const float4* t1 = (const float4*)&sm.r4.T[g][0][2 * v2 + 1][0];
    const float4* p0 = (const float4*)&sm.r4.T[g][1][2 * vp2][0];
    const float4* p1 = (const float4*)&sm.r4.T[g][1][2 * vp2 + 1][0];
    float a00 = 0.f, a01 = 0.f, a10 = 0.f, a11 = 0.f;   // 4 independent chains
#pragma unroll
    for (int d = 0; d < 16; d++) {
        float4 x0 = t0[d], x1 = t1[d], y0 = p0[d], y1 = p1[d];
        a00 += x0.x * y0.x + x0.y * y0.y + x0.z * y0.z + x0.w * y0.w;
        a01 += x0.x * y1.x + x0.y * y1.y + x0.z * y1.z + x0.w * y1.w;
        a10 += x1.x * y0.x + x1.y * y0.y + x1.z * y0.z + x1.w * y0.w;
        a11 += x1.x * y1.x + x1.y * y1.y + x1.z * y1.z + x1.w * y1.w;
    }
    float accs[2][2] = {{a00, a01}, {a10, a11}};
    float* fB = fOut + b * fBStride;
#pragma unroll
    for (int iv = 0; iv < 2; iv++)
#pragma unroll
        for (int jv = 0; jv < 2; jv++) {
            int v = 2 * v2 + iv, vp = 2 * vp2 + jv;
            float a = accs[iv][jv];
            if (axis == 2 || v != vp) {
                int e = e_pos(axis, c0, c1, v, vp);
                fB[(nbse + v * st) * EDIM + e] = a;
                atomicAdd(&sm.r4.ssl[g][e], a * a);
            }
        }
    __syncthreads();
    if (t < 184) {                                // flush 4x46 line sums -> global
        int gg = t / 46, e = t - gg * 46;
        float sv = sm.r4.ssl[gg][e];
        if (sv != 0.f) atomicAdd(ssOut + b * ssBStride + e * 32, sv);
    }
}

// ---------------- proj phase: 3xTF32 mma, 64x64 tiles ------------------------
__device__ __forceinline__ void proj_phase(Smem& sm, int bid) {
    int t = threadIdx.x;
    int lane = t & 31, w = t >> 5;
    int g = lane >> 2, tg = lane & 3;
    int mrow = (w & 3) << 4;          // warp m-offset within 64
    int nb = (w >> 2) << 5;           // warp n-offset within 64
    for (int task = bid; task < 384; task += NB) {
        int rowTile = task / 3;
        int rowBase = rowTile << 6, colBase = (task - rowTile * 3) << 6;
        float acc[4][4];
#pragma unroll
        for (int i = 0; i < 4; i++)
#pragma unroll
            for (int j = 0; j < 4; j++) acc[i][j] = 0.f;

        for (int k0 = 0; k0 < 128; k0 += 32) {
            __syncthreads();
#pragma unroll
            for (int it = 0; it < 2; it++) {
                int idx = t + it * 256;
                int rr = idx & 63, k4 = idx >> 6;
                float4 va = *(const float4*)(g_h + (rowBase + rr) * 128 + k0 + k4 * 4);
                float4 vb = *(const float4*)(g_Wcat + (colBase + rr) * 128 + k0 + k4 * 4);
                const float* vaf = (const float*)&va;
                const float* vbf = (const float*)&vb;
#pragma unroll
                for (int jj = 0; jj < 4; jj++) {
                    float av = vaf[jj];
                    float ah = __uint_as_float(__float_as_uint(av) & 0xFFFFE000u);
                    sm.p.Ah[k4 * 4 + jj][rr] = ah;
                    sm.p.Al[k4 * 4 + jj][rr] = av - ah;
                    float bv = vbf[jj];
                    float bh = __uint_as_float(__float_as_uint(bv) & 0xFFFFE000u);
                    sm.p.Bh[k4 * 4 + jj][rr] = bh;
                    sm.p.Bl[k4 * 4 + jj][rr] = bv - bh;
                }
            }
            __syncthreads();
#pragma unroll
            for (int ks = 0; ks < 4; ks++) {
                int kr = ks * 8;
                uint32_t ah[4], al[4];
                ah[0] = __float_as_uint(sm.p.Ah[kr + tg][mrow + g]);
                ah[1] = __float_as_uint(sm.p.Ah[kr + tg][mrow + g + 8]);
                ah[2] = __float_as_uint(sm.p.Ah[kr + tg + 4][mrow + g]);
                ah[3] = __float_as_uint(sm.p.Ah[kr + tg + 4][mrow + g + 8]);
                al[0] = __float_as_uint(sm.p.Al[kr + tg][mrow + g]);
                al[1] = __float_as_uint(sm.p.Al[kr + tg][mrow + g + 8]);
                al[2] = __float_as_uint(sm.p.Al[kr + tg + 4][mrow + g]);
                al[3] = __float_as_uint(sm.p.Al[kr + tg + 4][mrow + g + 8]);
#pragma unroll
                for (int ch = 0; ch < 4; ch++) {
                    int nn = nb + ch * 8 + g;
                    uint32_t bh0 = __float_as_uint(sm.p.Bh[kr + tg][nn]);
                    uint32_t bh1 = __float_as_uint(sm.p.Bh[kr + tg + 4][nn]);
                    uint32_t bl0 = __float_as_uint(sm.p.Bl[kr + tg][nn]);
                    uint32_t bl1 = __float_as_uint(sm.p.Bl[kr + tg + 4][nn]);
                    mma8(acc[ch], ah, bh0, bh1);     // hi*hi
                    mma8(acc[ch], ah, bl0, bl1);     // hi*lo
                    mma8(acc[ch], al, bh0, bh1);     // lo*hi
                }
            }
        }
#pragma unroll
        for (int ch = 0; ch < 4; ch++) {
            int col = colBase + nb + ch * 8 + 2 * tg;
            int row = rowBase + mrow + g;
            g_proj[row * PROJW + col]         = acc[ch][0] + g_bcat[col];
            g_proj[row * PROJW + col + 1]     = acc[ch][1] + g_bcat[col + 1];
            g_proj[(row + 8) * PROJW + col]     = acc[ch][2] + g_bcat[col];
            g_proj[(row + 8) * PROJW + col + 1] = acc[ch][3] + g_bcat[col + 1];
        }
    }
}

// ---------------- pipelined agg phase ----------------------------------------
__device__ __forceinline__ void agg_phase(Smem& sm, int bid) {
    int t = threadIdx.x;
    if (t < 92) sm.a.nrm2[t] = 1.f / (1e-6f + sqrtf(g_ss[t * 32]));  // both batches
    int r = t >> 4, c = t & 15;
    int task = bid;                         // 1536 tasks: exactly 3 per block
    float4 gv; float fv[3], qv[3]; int lnd[3], le[3];
    int curNb, curAxis, curC0, curC1, curSt, curB;
    {
        int b = task / 768, lt = task - b * 768;
        int axis = lt >> 8, line = lt & 255;
        int nb_, st, c0, c1; line_decode(axis, line, nb_, st, c0, c1);
        gv = *(const float4*)(g_proj + (b * NNODE + nb_ + r * st) * PROJW + 128 + c * 4);
#pragma unroll
        for (int ii = 0; ii < 3; ii++) {
            int l = t + ii * 256; int nd = l / 48, e = l - nd * 48;
            lnd[ii] = nd; le[ii] = e;
            if (e < 46) {
                int n = nb_ + nd * st;
                fv[ii] = g_f[(b * NNODE + n) * EDIM + e];
                qv[ii] = g_fpn[n * EDIM + e];
            }
        }
        curNb = nb_; curAxis = axis; curC0 = c0; curC1 = c1; curSt = st; curB = b;
    }
    bool have = true;
    while (have) {
        int nb_ = curNb, axis = curAxis, c0 = curC0, c1 = curC1, st = curSt, b = curB;
        __syncthreads();                    // prev compute done; nrm2 visible
        *(float4*)&sm.a.Gs[r][c * 4] = gv;
#pragma unroll
        for (int ii = 0; ii < 3; ii++)
            sm.a.fs[lnd[ii]][le[ii]] = (le[ii] < 46)
                ? fv[ii] * sm.a.nrm2[b * 46 + le[ii]] + qv[ii] : -1e30f;
        task += NB; have = task < 1536;
        if (have) {                         // prefetch next
            int b2 = task / 768, lt = task - b2 * 768;
            int axis2 = lt >> 8, line2 = lt & 255;
            int n2b, st2, c02, c12; line_decode(axis2, line2, n2b, st2, c02, c12);
            gv = *(const float4*)(g_proj + (b2 * NNODE + n2b + r * st2) * PROJW + 128 + c * 4);
#pragma unroll
            for (int ii = 0; ii < 3; ii++) {
                if (le[ii] < 46) {
                    int n = n2b + lnd[ii] * st2;
                    fv[ii] = g_f[(b2 * NNODE + n) * EDIM + le[ii]];
                    qv[ii] = g_fpn[n * EDIM + le[ii]];
                }
            }
            curNb = n2b; curAxis = axis2; curC0 = c02; curC1 = c12; curSt = st2; curB = b2;
        }
        __syncthreads();
        int ty = r, tx = c;
        float a0 = sm.a.fs[ty][tx], a1 = sm.a.fs[ty][tx + 16], a2 = sm.a.fs[ty][tx + 32];
        float m = fmaxf(a0, fmaxf(a1, a2));
#pragma unroll
        for (int o = 8; o; o >>= 1) m = fmaxf(m, __shfl_xor_sync(0xffffffffu, m, o));
        float e0 = expf(a0 - m), e1 = expf(a1 - m), e2 = expf(a2 - m);
        float z = e0 + e1 + e2;
#pragma unroll
        for (int o = 8; o; o >>= 1) z += __shfl_xor_sync(0xffffffffu, z, o);
        float invZ = 1.f / z;
        sm.a.fs[ty][tx] = e0; sm.a.fs[ty][tx + 16] = e1; sm.a.fs[ty][tx + 32] = e2;
        __syncwarp();

        float4 acc = {0.f, 0.f, 0.f, 0.f};
#pragma unroll
        for (int vp = 0; vp < 16; vp++) {
            float w;
            if (axis == 2)      w = sm.a.fs[ty][c0 + c1 + vp];
            else if (vp == ty)  w = 0.f;
            else if (axis == 0) w = sm.a.fs[ty][vp < ty ? vp : vp + 30];
            else                w = sm.a.fs[ty][c0 + (vp < ty ? vp : vp + 15)];
            float4 gg = *(const float4*)&sm.a.Gs[vp][tx * 4];
            acc.x += w * gg.x; acc.y += w * gg.y; acc.z += w * gg.z; acc.w += w * gg.w;
        }
        acc.x *= invZ; acc.y *= invZ; acc.z *= invZ; acc.w *= invZ;
        int n = nb_ + ty * st;
        *(float4*)&g_y[axis][(b * NNODE + n) * 64 + tx * 4] = acc;
    }
}

// ---------------- resid GEMM tile (scalar FFMA; small) -----------------------
__device__ __forceinline__ void resid_tile(Smem& sm, int task,
        const float* __restrict__ rw, const float* __restrict__ rb,
        float* __restrict__ outp, int last) {
    int rowBase = (task >> 1) << 6, colBase = (task & 1) << 6;
    int t = threadIdx.x, tx = t & 15, ty = t >> 4;
    const int AX = BCNT * NNODE * 64;
    float acc[4][4] = {};
    for (int k0 = 0; k0 < 64; k0 += 32) {
#pragma unroll
        for (int it = 0; it < 2; it++) {
            int idx = t + it * 256;
            int r = idx & 63, k4 = idx >> 6;
            const float* yb = &g_y[0][(rowBase + r) * 64 + k0 + k4 * 4];
            float4 v0 = *(const float4*)yb;
            float4 v1 = *(const float4*)(yb + AX);
            float4 v2 = *(const float4*)(yb + 2 * AX);
            sm.g.A[k4 * 4 + 0][r] = v0.x + v1.x + v2.x;
            sm.g.A[k4 * 4 + 1][r] = v0.y + v1.y + v2.y;
            sm.g.A[k4 * 4 + 2][r] = v0.z + v1.z + v2.z;
            sm.g.A[k4 * 4 + 3][r] = v0.w + v1.w + v2.w;
            float4 w = *(const float4*)(rw + (colBase + r) * 64 + k0 + k4 * 4);
            sm.g.B[k4 * 4 + 0][r] = w.x; sm.g.B[k4 * 4 + 1][r] = w.y;
            sm.g.B[k4 * 4 + 2][r] = w.z; sm.g.B[k4 * 4 + 3][r] = w.w;
        }
        __syncthreads();
#pragma unroll
        for (int kk = 0; kk < 32; kk++) {
            float4 a = *(const float4*)&sm.g.A[kk][ty * 4];
            float4 b = *(const float4*)&sm.g.B[kk][tx * 4];
            float av[4] = {a.x, a.y, a.z, a.w};
            float bv[4] = {b.x, b.y, b.z, b.w};
#pragma unroll
            for (int i = 0; i < 4; i++)
#pragma unroll
                for (int j = 0; j < 4; j++) acc[i][j] += av[i] * bv[j];
        }
        __syncthreads();
    }
#pragma unroll
    for (int i = 0; i < 4; i++) {
        int row = rowBase + ty * 4 + i;
#pragma unroll
        for (int j = 0; j < 4; j++) {
            int c = colBase + tx * 4 + j;
            float val = acc[i][j] + rb[c] + g_h[row * 128 + c];
            if (last) {
                int b = row >> 12, n = row & 4095;
                outp[(((b << 7) + c) << 12) + n] = val;
            } else {
                g_h[row * 128 + c] = val;
            }
        }
    }
}

// ---------------- the single persistent kernel -------------------------------
__global__ __launch_bounds__(NT, 4) void k_all(
        const float* __restrict__ x,
        const float* __restrict__ Gw, const float* __restrict__ Gb,
        const float* __restrict__ thw, const float* __restrict__ thb,
        const float* __restrict__ phw, const float* __restrict__ phb,
        const float* __restrict__ rw, const float* __restrict__ rb,
        const float* __restrict__ gthw, const float* __restrict__ gthb,
        const float* __restrict__ gphw, const float* __restrict__ gphb,
        float* __restrict__ outp) {
    __shared__ Smem sm;
    const int t = threadIdx.x, bid = blockIdx.x;
    const int gtid = bid * NT + t, gs = NB * NT;

    // ---- phase PREP ----
    // coalesced transpose via 32x32 smem tiles: 1024 tiles
    for (int task = bid; task < 1024; task += NB) {
        int b = task >> 9, ct = (task >> 7) & 3, nt = task & 127;
        __syncthreads();
        for (int l = t; l < 1024; l += NT) {
            int cc = l >> 5, nn = l & 31;
            sm.tr.tile[cc][nn] = x[(((b << 7) + (ct << 5) + cc) << 12) + (nt << 5) + nn];
        }
        __syncthreads();
        for (int l = t; l < 1024; l += NT) {
            int cc = l & 31, nn = l >> 5;
            g_h[(((b << 12) + (nt << 5) + nn) << 7) + (ct << 5) + cc] = sm.tr.tile[cc][nn];
        }
    }
    for (int idx = gtid; idx < PROJW * CDIM; idx += gs) {
        int r = idx >> 7, k = idx & 127;
        g_Wcat[idx] = (r < 64) ? thw[r * 128 + k]
                    : (r < 128) ? phw[(r - 64) * 128 + k]
                    : Gw[(r - 128) * 128 + k];
    }
    for (int idx = gtid; idx < PROJW; idx += gs)
        g_bcat[idx] = (idx < 64) ? thb[idx] : (idx < 128) ? phb[idx - 64] : Gb[idx - 128];
    for (int idx = gtid; idx < 46; idx += gs) g_ssfp[idx * 32] = 0.f;
    for (int idx = gtid; idx < NNODE * 64; idx += gs) {
        int n = idx >> 6, d = idx & 63;
        int i = n >> 8, j = (n >> 4) & 15, k = n & 15;
        float p0 = i * (1.f / 15.f) - 0.5f;
        float p1 = j * (1.f / 15.f) - 0.5f;
        float p2 = k * (1.f / 15.f) - 0.5f;
        g_pth[idx] = p0 * gthw[d * 3] + p1 * gthw[d * 3 + 1] + p2 * gthw[d * 3 + 2] + gthb[d];
        g_pph[idx] = p0 * gphw[d * 3] + p1 * gphw[d * 3 + 1] + p2 * gphw[d * 3 + 2] + gphb[d];
    }
    gsync();

    // ---- phase FP: geo Gram lines (192 tasks, 4 lines each) ----
    if (bid < 192)
        gram4(sm, bid, g_pth, g_pph, 64, 0, g_fp, 0, g_ssfp, 0);
    gsync();

    for (int r = 0; r < 3; r++) {
        // ---- phase P: projection GEMM (3xTF32 mma) + zero g_ss (+FPN on r0) ----
        if (bid == 0 && t < 92) g_ss[t * 32] = 0.f;
        proj_phase(sm, bid);
        if (r == 0) {
            // normalized relu'd f_p (g_fp/g_ssfp finalized before prev gsync)
            for (int idx = gtid; idx < NNODE * EDIM; idx += gs) {
                int e = idx % EDIM;
                g_fpn[idx] = fmaxf(g_fp[idx] / (1e-6f + sqrtf(g_ssfp[e * 32])), 0.f);
            }
        }
        gsync();

        // ---- phase G: f Gram lines (384 tasks, 4 lines each) ----
        if (bid < 384)
            gram4(sm, bid, g_proj, g_proj + 64, PROJW, NNODE * PROJW,
                  g_f, NNODE * EDIM, g_ss, EDIM * 32);
        gsync();

        // ---- phase A: softmax + aggregate ----
        agg_phase(sm, bid);
        gsync();

        // ---- phase R: residual GEMM ----
        for (int task = bid; task < 256; task += NB)
            resid_tile(sm, task, rw, rb, outp, r == 2);
        if (r < 2) gsync();
    }
}

// ---------------------------------------------------------------------------
extern "C" void kernel_launch(void* const* d_in, const int* in_sizes, int n_in,
                              void* d_out, int out_size) {
    const float* x    = (const float*)d_in[0];
    const float* G_w  = (const float*)d_in[1];
    const float* G_b  = (const float*)d_in[2];
    const float* th_w = (const float*)d_in[3];
    const float* th_b = (const float*)d_in[4];
    const float* ph_w = (const float*)d_in[5];
    const float* ph_b = (const float*)d_in[6];
    const float* r_w  = (const float*)d_in[7];
    const float* r_b  = (const float*)d_in[8];
    const float* gt_w = (const float*)d_in[9];
    const float* gt_b = (const float*)d_in[10];
    const float* gp_w = (const float*)d_in[11];
    const float* gp_b = (const float*)d_in[12];
    float* out = (float*)d_out;

    k_all<<<NB, NT>>>(x, G_w, G_b, th_w, th_b, ph_w, ph_b, r_w, r_b,
                      gt_w, gt_b, gp_w, gp_b, out);
}

// round 10
// speedup vs baseline: 1.2834x; 1.1678x over previous
#include <cuda_runtime.h>
#include <cstdint>

// Fixed shapes: B=2, C=128, D=H=W=16
#define NNODE 4096
#define CDIM  128
#define EDIM  46
#define BCNT  2
#define PROJW 192   // theta(64) | phi(64) | G(64)

// ---------------- scratch (device globals) ---------------------------------
__device__ float g_h[BCNT * NNODE * CDIM];
__device__ float g_proj[BCNT * NNODE * PROJW];
__device__ float g_f[BCNT * NNODE * EDIM];
__device__ float g_fp[NNODE * EDIM];
__device__ float g_fpn[NNODE * EDIM];             // relu(l2norm(f_p)) precomputed
__device__ float g_pth[NNODE * 64];
__device__ float g_pph[NNODE * 64];
__device__ float g_ss[92 * 32];
__device__ float g_ssfp[46 * 32];
__device__ float g_Wcat[PROJW * CDIM];
__device__ float g_bcat[PROJW];
__device__ float g_y[3][BCNT * NNODE * 64];

// line decode: axis0 line=(j,k) step 256; axis1 line=(i,k) step 16; axis2 line=(i,j) step 1
__device__ __forceinline__ void line_decode(int axis, int line,
                                            int& nbase, int& step, int& c0, int& c1) {
    if (axis == 0)      { nbase = line; step = 256; c0 = 0; c1 = 0; }
    else if (axis == 1) { c0 = line >> 4; nbase = (c0 << 8) | (line & 15); step = 16; c1 = 0; }
    else                { c0 = line >> 4; c1 = line & 15; nbase = (c0 << 8) | (c1 << 4); step = 1; }
}
__device__ __forceinline__ int e_pos(int axis, int c0, int c1, int v, int vp) {
    if (axis == 0) return vp < v ? vp : vp + 30;
    if (axis == 1) return c0 + (vp < v ? vp : vp + 15);
    return c0 + c1 + vp;                          // includes self
}

// ---------------- 3xTF32 mma helper ------------------------------------------
__device__ __forceinline__ void mma8(float* c, const uint32_t* a, uint32_t b0, uint32_t b1) {
    asm volatile("mma.sync.aligned.m16n8k8.row.col.f32.tf32.tf32.f32 "
                 "{%0,%1,%2,%3},{%4,%5,%6,%7},{%8,%9},{%0,%1,%2,%3};\n"
                 : "+f"(c[0]), "+f"(c[1]), "+f"(c[2]), "+f"(c[3])
                 : "r"(a[0]), "r"(a[1]), "r"(a[2]), "r"(a[3]), "r"(b0), "r"(b1));
}

// ---------------- K1: prep (transpose + Wcat + bcat + geo + zero ssfp) -------
__global__ __launch_bounds__(256) void k_prep(
        const float* __restrict__ x,
        const float* __restrict__ Gw, const float* __restrict__ Gb,
        const float* __restrict__ thw, const float* __restrict__ thb,
        const float* __restrict__ phw, const float* __restrict__ phb,
        const float* __restrict__ gthw, const float* __restrict__ gthb,
        const float* __restrict__ gphw, const float* __restrict__ gphb) {
    __shared__ float tile[32][33];
    const int t = threadIdx.x, bid = blockIdx.x;
    const int gtid = bid * 256 + t, gs = gridDim.x * 256;

    // coalesced transpose via 32x32 smem tiles: 1024 tiles, 2 per block
    for (int task = bid; task < 1024; task += gridDim.x) {
        int b = task >> 9, ct = (task >> 7) & 3, nt = task & 127;
        __syncthreads();
        for (int l = t; l < 1024; l += 256) {
            int cc = l >> 5, nn = l & 31;
            tile[cc][nn] = x[(((b << 7) + (ct << 5) + cc) << 12) + (nt << 5) + nn];
        }
        __syncthreads();
        for (int l = t; l < 1024; l += 256) {
            int cc = l & 31, nn = l >> 5;
            g_h[(((b << 12) + (nt << 5) + nn) << 7) + (ct << 5) + cc] = tile[cc][nn];
        }
    }
    for (int idx = gtid; idx < PROJW * CDIM; idx += gs) {
        int r = idx >> 7, k = idx & 127;
        g_Wcat[idx] = (r < 64) ? thw[r * 128 + k]
                    : (r < 128) ? phw[(r - 64) * 128 + k]
                    : Gw[(r - 128) * 128 + k];
    }
    for (int idx = gtid; idx < PROJW; idx += gs)
        g_bcat[idx] = (idx < 64) ? thb[idx] : (idx < 128) ? phb[idx - 64] : Gb[idx - 128];
    for (int idx = gtid; idx < 46; idx += gs) g_ssfp[idx * 32] = 0.f;
    for (int idx = gtid; idx < NNODE * 64; idx += gs) {
        int n = idx >> 6, d = idx & 63;
        int i = n >> 8, j = (n >> 4) & 15, k = n & 15;
        float p0 = i * (1.f / 15.f) - 0.5f;
        float p1 = j * (1.f / 15.f) - 0.5f;
        float p2 = k * (1.f / 15.f) - 0.5f;
        g_pth[idx] = p0 * gthw[d * 3] + p1 * gthw[d * 3 + 1] + p2 * gthw[d * 3 + 2] + gthb[d];
        g_pph[idx] = p0 * gphw[d * 3] + p1 * gphw[d * 3 + 1] + p2 * gphw[d * 3 + 2] + gphb[d];
    }
}

// ---------------- K2: gram (4 lines/block, 2x2 register tiling) --------------
// mode 0: f_p from pth/pph (grid 192). mode 1: f from proj (grid 384).
__global__ __launch_bounds__(256) void k_gram(int mode) {
    __shared__ float T[4][2][16][68];
    __shared__ float ssl[4][48];
    int t = threadIdx.x;
    int L0 = blockIdx.x << 2;
    int b = L0 / 768, lt = L0 - b * 768;
    int axis = lt >> 8, lineBase = lt & 255;     // groups of 4 never cross axis/batch

    const float* thB; const float* phB; int stride; float* fB; float* ssB;
    if (mode) {
        thB = g_proj + b * NNODE * PROJW; phB = thB + 64; stride = PROJW;
        fB = g_f + b * NNODE * EDIM; ssB = g_ss + b * EDIM * 32;
    } else {
        thB = g_pth; phB = g_pph; stride = 64;
        fB = g_fp; ssB = g_ssfp;
    }

    if (t < 192) (&ssl[0][0])[t] = 0.f;

    // cooperative load: 4 lines x 2 tiles x 16 rows x 64 floats; 8x LDG.128/thread
#pragma unroll
    for (int i = 0; i < 8; i++) {
        int c = t + (i << 8);
        int tl = c >> 8;                          // 0..7
        int g = tl >> 1, which = tl & 1;
        int r = (c >> 4) & 15, off = c & 15;
        int nbse, st, c0, c1; line_decode(axis, lineBase + g, nbse, st, c0, c1);
        const float* src = (which ? phB : thB) + (nbse + r * st) * stride + off * 4;
        *(float4*)&T[g][which][r][off * 4] = *(const float4*)src;
    }
    __syncthreads();

    int g = t >> 6, s = t & 63;
    int v2 = s >> 3, vp2 = s & 7;
    int nbse, st, c0, c1; line_decode(axis, lineBase + g, nbse, st, c0, c1);
    const float4* t0 = (const float4*)&T[g][0][2 * v2][0];
    const float4* t1 = (const float4*)&T[g][0][2 * v2 + 1][0];
    const float4* p0 = (const float4*)&T[g][1][2 * vp2][0];
    const float4* p1 = (const float4*)&T[g][1][2 * vp2 + 1][0];
    float a00 = 0.f, a01 = 0.f, a10 = 0.f, a11 = 0.f;   // 4 independent chains
#pragma unroll
    for (int d = 0; d < 16; d++) {
        float4 x0 = t0[d], x1 = t1[d], y0 = p0[d], y1 = p1[d];
        a00 += x0.x * y0.x + x0.y * y0.y + x0.z * y0.z + x0.w * y0.w;
        a01 += x0.x * y1.x + x0.y * y1.y + x0.z * y1.z + x0.w * y1.w;
        a10 += x1.x * y0.x + x1.y * y0.y + x1.z * y0.z + x1.w * y0.w;
        a11 += x1.x * y1.x + x1.y * y1.y + x1.z * y1.z + x1.w * y1.w;
    }
    float accs[2][2] = {{a00, a01}, {a10, a11}};
#pragma unroll
    for (int iv = 0; iv < 2; iv++)
#pragma unroll
        for (int jv = 0; jv < 2; jv++) {
            int v = 2 * v2 + iv, vp = 2 * vp2 + jv;
            float a = accs[iv][jv];
            if (axis == 2 || v != vp) {
                int e = e_pos(axis, c0, c1, v, vp);
                fB[(nbse + v * st) * EDIM + e] = a;
                atomicAdd(&ssl[g][e], a * a);
            }
        }
    __syncthreads();
    if (t < 184) {                                // flush 4x46 line sums -> global
        int gg = t / 46, e = t - gg * 46;
        float sv = ssl[gg][e];
        if (sv != 0.f) atomicAdd(ssB + e * 32, sv);
    }
}

// ---------------- K3: proj GEMM (3xTF32 mma, 64x64 tile/block, grid 384) -----
// Also zeroes g_ss (block 0) for this round's gram atomics, and on do_fpn
// computes the normalized relu'd f_p table (grid-strided).
__global__ __launch_bounds__(256) void k_proj(int do_fpn) {
    __shared__ float Ah[32][72], Al[32][72], Bh[32][72], Bl[32][72];
    int t = threadIdx.x;
    if (blockIdx.x == 0 && t < 92) g_ss[t * 32] = 0.f;
    if (do_fpn) {
        int gtid = blockIdx.x * 256 + t, gs = gridDim.x * 256;
        for (int idx = gtid; idx < NNODE * EDIM; idx += gs) {
            int e = idx % EDIM;
            g_fpn[idx] = fmaxf(g_fp[idx] / (1e-6f + sqrtf(g_ssfp[e * 32])), 0.f);
        }
    }
    int lane = t & 31, w = t >> 5;
    int g = lane >> 2, tg = lane & 3;
    int mrow = (w & 3) << 4;          // warp m-offset within 64
    int nb = (w >> 2) << 5;           // warp n-offset within 64
    int task = blockIdx.x;
    int rowTile = task / 3;
    int rowBase = rowTile << 6, colBase = (task - rowTile * 3) << 6;
    float acc[4][4];
#pragma unroll
    for (int i = 0; i < 4; i++)
#pragma unroll
        for (int j = 0; j < 4; j++) acc[i][j] = 0.f;

    for (int k0 = 0; k0 < 128; k0 += 32) {
        __syncthreads();
#pragma unroll
        for (int it = 0; it < 2; it++) {
            int idx = t + it * 256;
            int rr = idx & 63, k4 = idx >> 6;
            float4 va = *(const float4*)(g_h + (rowBase + rr) * 128 + k0 + k4 * 4);
            float4 vb = *(const float4*)(g_Wcat + (colBase + rr) * 128 + k0 + k4 * 4);
            const float* vaf = (const float*)&va;
            const float* vbf = (const float*)&vb;
#pragma unroll
            for (int jj = 0; jj < 4; jj++) {
                float av = vaf[jj];
                float ah = __uint_as_float(__float_as_uint(av) & 0xFFFFE000u);
                Ah[k4 * 4 + jj][rr] = ah;
                Al[k4 * 4 + jj][rr] = av - ah;
                float bv = vbf[jj];
                float bh = __uint_as_float(__float_as_uint(bv) & 0xFFFFE000u);
                Bh[k4 * 4 + jj][rr] = bh;
                Bl[k4 * 4 + jj][rr] = bv - bh;
            }
        }
        __syncthreads();
#pragma unroll
        for (int ks = 0; ks < 4; ks++) {
            int kr = ks * 8;
            uint32_t ah[4], al[4];
            ah[0] = __float_as_uint(Ah[kr + tg][mrow + g]);
            ah[1] = __float_as_uint(Ah[kr + tg][mrow + g + 8]);
            ah[2] = __float_as_uint(Ah[kr + tg + 4][mrow + g]);
            ah[3] = __float_as_uint(Ah[kr + tg + 4][mrow + g + 8]);
            al[0] = __float_as_uint(Al[kr + tg][mrow + g]);
            al[1] = __float_as_uint(Al[kr + tg][mrow + g + 8]);
            al[2] = __float_as_uint(Al[kr + tg + 4][mrow + g]);
            al[3] = __float_as_uint(Al[kr + tg + 4][mrow + g + 8]);
#pragma unroll
            for (int ch = 0; ch < 4; ch++) {
                int nn = nb + ch * 8 + g;
                uint32_t bh0 = __float_as_uint(Bh[kr + tg][nn]);
                uint32_t bh1 = __float_as_uint(Bh[kr + tg + 4][nn]);
                uint32_t bl0 = __float_as_uint(Bl[kr + tg][nn]);
                uint32_t bl1 = __float_as_uint(Bl[kr + tg + 4][nn]);
                mma8(acc[ch], ah, bh0, bh1);     // hi*hi
                mma8(acc[ch], ah, bl0, bl1);     // hi*lo
                mma8(acc[ch], al, bh0, bh1);     // lo*hi
            }
        }
    }
#pragma unroll
    for (int ch = 0; ch < 4; ch++) {
        int col = colBase + nb + ch * 8 + 2 * tg;
        int row = rowBase + mrow + g;
        g_proj[row * PROJW + col]           = acc[ch][0] + g_bcat[col];
        g_proj[row * PROJW + col + 1]       = acc[ch][1] + g_bcat[col + 1];
        g_proj[(row + 8) * PROJW + col]     = acc[ch][2] + g_bcat[col];
        g_proj[(row + 8) * PROJW + col + 1] = acc[ch][3] + g_bcat[col + 1];
    }
}

// ---------------- K4: softmax + aggregate (grid 1536, 1 line each) -----------
__global__ __launch_bounds__(256) void k_agg() {
    __shared__ float Gs[16][68];
    __shared__ float fs[16][48];
    __shared__ float nrm2[92];
    int t = threadIdx.x;
    int task = blockIdx.x;
    int b = task / 768, lt = task - b * 768;
    int axis = lt >> 8, line = lt & 255;
    int nb_, st, c0, c1; line_decode(axis, line, nb_, st, c0, c1);

    if (t < 92) nrm2[t] = 1.f / (1e-6f + sqrtf(g_ss[t * 32]));

    int r = t >> 4, c = t & 15;
    // loads into registers (no smem dependency yet)
    float4 gv = *(const float4*)(g_proj + (b * NNODE + nb_ + r * st) * PROJW + 128 + c * 4);
    float fv[3], qv[3]; int lnd[3], le[3];
#pragma unroll
    for (int ii = 0; ii < 3; ii++) {
        int l = t + ii * 256; lnd[ii] = l / 48; le[ii] = l - lnd[ii] * 48;
        if (le[ii] < 46) {
            int n = nb_ + lnd[ii] * st;
            fv[ii] = g_f[(b * NNODE + n) * EDIM + le[ii]];
            qv[ii] = g_fpn[n * EDIM + le[ii]];
        }
    }
    __syncthreads();                              // nrm2 visible
    *(float4*)&Gs[r][c * 4] = gv;
#pragma unroll
    for (int ii = 0; ii < 3; ii++)
        fs[lnd[ii]][le[ii]] = (le[ii] < 46)
            ? fv[ii] * nrm2[b * 46 + le[ii]] + qv[ii] : -1e30f;
    __syncthreads();

    int ty = r, tx = c;
    float a0 = fs[ty][tx], a1 = fs[ty][tx + 16], a2 = fs[ty][tx + 32];
    float m = fmaxf(a0, fmaxf(a1, a2));
#pragma unroll
    for (int o = 8; o; o >>= 1) m = fmaxf(m, __shfl_xor_sync(0xffffffffu, m, o));
    float e0 = expf(a0 - m), e1 = expf(a1 - m), e2 = expf(a2 - m);
    float z = e0 + e1 + e2;
#pragma unroll
    for (int o = 8; o; o >>= 1) z += __shfl_xor_sync(0xffffffffu, z, o);
    float invZ = 1.f / z;
    fs[ty][tx] = e0; fs[ty][tx + 16] = e1; fs[ty][tx + 32] = e2;
    __syncwarp();

    float4 acc = {0.f, 0.f, 0.f, 0.f};
#pragma unroll
    for (int vp = 0; vp < 16; vp++) {
        float w;
        if (axis == 2)      w = fs[ty][c0 + c1 + vp];
        else if (vp == ty)  w = 0.f;
        else if (axis == 0) w = fs[ty][vp < ty ? vp : vp + 30];
        else                w = fs[ty][c0 + (vp < ty ? vp : vp + 15)];
        float4 gg = *(const float4*)&Gs[vp][tx * 4];
        acc.x += w * gg.x; acc.y += w * gg.y; acc.z += w * gg.z; acc.w += w * gg.w;
    }
    acc.x *= invZ; acc.y *= invZ; acc.z *= invZ; acc.w *= invZ;
    int n = nb_ + ty * st;
    *(float4*)&g_y[axis][(b * NNODE + n) * 64 + tx * 4] = acc;
}

// ---------------- K5: residual GEMM (grid 256, 64x64 tile) -------------------
__global__ __launch_bounds__(256) void k_resid(const float* __restrict__ rw,
                                               const float* __restrict__ rb,
                                               float* __restrict__ outp, int last) {
    __shared__ float A[32][68], B[32][68];
    int task = blockIdx.x;
    int rowBase = (task >> 1) << 6, colBase = (task & 1) << 6;
    int t = threadIdx.x, tx = t & 15, ty = t >> 4;
    const int AX = BCNT * NNODE * 64;
    float acc[4][4] = {};
    for (int k0 = 0; k0 < 64; k0 += 32) {
#pragma unroll
        for (int it = 0; it < 2; it++) {
            int idx = t + it * 256;
            int r = idx & 63, k4 = idx >> 6;
            const float* yb = &g_y[0][(rowBase + r) * 64 + k0 + k4 * 4];
            float4 v0 = *(const float4*)yb;
            float4 v1 = *(const float4*)(yb + AX);
            float4 v2 = *(const float4*)(yb + 2 * AX);
            A[k4 * 4 + 0][r] = v0.x + v1.x + v2.x;
            A[k4 * 4 + 1][r] = v0.y + v1.y + v2.y;
            A[k4 * 4 + 2][r] = v0.z + v1.z + v2.z;
            A[k4 * 4 + 3][r] = v0.w + v1.w + v2.w;
            float4 w = *(const float4*)(rw + (colBase + r) * 64 + k0 + k4 * 4);
            B[k4 * 4 + 0][r] = w.x; B[k4 * 4 + 1][r] = w.y;
            B[k4 * 4 + 2][r] = w.z; B[k4 * 4 + 3][r] = w.w;
        }
        __syncthreads();
#pragma unroll
        for (int kk = 0; kk < 32; kk++) {
            float4 a = *(const float4*)&A[kk][ty * 4];
            float4 b = *(const float4*)&B[kk][tx * 4];
            float av[4] = {a.x, a.y, a.z, a.w};
            float bv[4] = {b.x, b.y, b.z, b.w};
#pragma unroll
            for (int i = 0; i < 4; i++)
#pragma unroll
                for (int j = 0; j < 4; j++) acc[i][j] += av[i] * bv[j];
        }
        __syncthreads();
    }
#pragma unroll
    for (int i = 0; i < 4; i++) {
        int row = rowBase + ty * 4 + i;
#pragma unroll
        for (int j = 0; j < 4; j++) {
            int c = colBase + tx * 4 + j;
            float val = acc[i][j] + rb[c] + g_h[row * 128 + c];
            if (last) {
                int b = row >> 12, n = row & 4095;
                outp[(((b << 7) + c) << 12) + n] = val;
            } else {
                g_h[row * 128 + c] = val;
            }
        }
    }
}

// ---------------------------------------------------------------------------
extern "C" void kernel_launch(void* const* d_in, const int* in_sizes, int n_in,
                              void* d_out, int out_size) {
    const float* x    = (const float*)d_in[0];
    const float* G_w  = (const float*)d_in[1];
    const float* G_b  = (const float*)d_in[2];
    const float* th_w = (const float*)d_in[3];
    const float* th_b = (const float*)d_in[4];
    const float* ph_w = (const float*)d_in[5];
    const float* ph_b = (const float*)d_in[6];
    const float* r_w  = (const float*)d_in[7];
    const float* r_b  = (const float*)d_in[8];
    const float* gt_w = (const float*)d_in[9];
    const float* gt_b = (const float*)d_in[10];
    const float* gp_w = (const float*)d_in[11];
    const float* gp_b = (const float*)d_in[12];
    float* out = (float*)d_out;

    k_prep<<<512, 256>>>(x, G_w, G_b, th_w, th_b, ph_w, ph_b,
                         gt_w, gt_b, gp_w, gp_b);
    k_gram<<<192, 256>>>(0);                       // f_p lines

    for (int r = 0; r < 3; r++) {
        k_proj<<<384, 256>>>(r == 0 ? 1 : 0);      // + zero g_ss, + FPN on r0
        k_gram<<<384, 256>>>(1);                   // f lines
        k_agg<<<1536, 256>>>();
        k_resid<<<256, 256>>>(r_w, r_b, out, r == 2);
    }
}

// round 11
// speedup vs baseline: 1.3007x; 1.0135x over previous
#include <cuda_runtime.h>
#include <cstdint>

// Fixed shapes: B=2, C=128, D=H=W=16
#define NNODE 4096
#define CDIM  128
#define EDIM  46
#define BCNT  2
#define PROJW 192   // theta(64) | phi(64) | G(64)

// ---------------- scratch (device globals) ---------------------------------
__device__ float g_h[BCNT * NNODE * CDIM];
__device__ float g_proj[BCNT * NNODE * PROJW];
__device__ float g_f[BCNT * NNODE * EDIM];
__device__ float g_fp[NNODE * EDIM];
__device__ float g_fpn[NNODE * EDIM];             // relu(l2norm(f_p)) precomputed
__device__ float g_pth[NNODE * 64];
__device__ float g_pph[NNODE * 64];
__device__ float g_ss[92 * 32];
__device__ float g_ssfp[46 * 32];
__device__ float g_Wcat[PROJW * CDIM];
__device__ float g_bcat[PROJW];
__device__ float g_y[3][BCNT * NNODE * 64];

// line decode: axis0 line=(j,k) step 256; axis1 line=(i,k) step 16; axis2 line=(i,j) step 1
__device__ __forceinline__ void line_decode(int axis, int line,
                                            int& nbase, int& step, int& c0, int& c1) {
    if (axis == 0)      { nbase = line; step = 256; c0 = 0; c1 = 0; }
    else if (axis == 1) { c0 = line >> 4; nbase = (c0 << 8) | (line & 15); step = 16; c1 = 0; }
    else                { c0 = line >> 4; c1 = line & 15; nbase = (c0 << 8) | (c1 << 4); step = 1; }
}
__device__ __forceinline__ int e_pos(int axis, int c0, int c1, int v, int vp) {
    if (axis == 0) return vp < v ? vp : vp + 30;
    if (axis == 1) return c0 + (vp < v ? vp : vp + 15);
    return c0 + c1 + vp;                          // includes self
}

// ---------------- 3xTF32 mma helper ------------------------------------------
__device__ __forceinline__ void mma8(float* c, const uint32_t* a, uint32_t b0, uint32_t b1) {
    asm volatile("mma.sync.aligned.m16n8k8.row.col.f32.tf32.tf32.f32 "
                 "{%0,%1,%2,%3},{%4,%5,%6,%7},{%8,%9},{%0,%1,%2,%3};\n"
                 : "+f"(c[0]), "+f"(c[1]), "+f"(c[2]), "+f"(c[3])
                 : "r"(a[0]), "r"(a[1]), "r"(a[2]), "r"(a[3]), "r"(b0), "r"(b1));
}

// ---------------- K1: prep (transpose + Wcat + bcat + geo + zero ssfp) -------
__global__ __launch_bounds__(256) void k_prep(
        const float* __restrict__ x,
        const float* __restrict__ Gw, const float* __restrict__ Gb,
        const float* __restrict__ thw, const float* __restrict__ thb,
        const float* __restrict__ phw, const float* __restrict__ phb,
        const float* __restrict__ gthw, const float* __restrict__ gthb,
        const float* __restrict__ gphw, const float* __restrict__ gphb) {
    __shared__ float tile[32][33];
    const int t = threadIdx.x, bid = blockIdx.x;
    const int gtid = bid * 256 + t, gs = gridDim.x * 256;

    // coalesced transpose via 32x32 smem tiles: 1024 tiles, 2 per block
    for (int task = bid; task < 1024; task += gridDim.x) {
        int b = task >> 9, ct = (task >> 7) & 3, nt = task & 127;
        __syncthreads();
        for (int l = t; l < 1024; l += 256) {
            int cc = l >> 5, nn = l & 31;
            tile[cc][nn] = x[(((b << 7) + (ct << 5) + cc) << 12) + (nt << 5) + nn];
        }
        __syncthreads();
        for (int l = t; l < 1024; l += 256) {
            int cc = l & 31, nn = l >> 5;
            g_h[(((b << 12) + (nt << 5) + nn) << 7) + (ct << 5) + cc] = tile[cc][nn];
        }
    }
    for (int idx = gtid; idx < PROJW * CDIM; idx += gs) {
        int r = idx >> 7, k = idx & 127;
        g_Wcat[idx] = (r < 64) ? thw[r * 128 + k]
                    : (r < 128) ? phw[(r - 64) * 128 + k]
                    : Gw[(r - 128) * 128 + k];
    }
    for (int idx = gtid; idx < PROJW; idx += gs)
        g_bcat[idx] = (idx < 64) ? thb[idx] : (idx < 128) ? phb[idx - 64] : Gb[idx - 128];
    for (int idx = gtid; idx < 46; idx += gs) g_ssfp[idx * 32] = 0.f;
    for (int idx = gtid; idx < NNODE * 64; idx += gs) {
        int n = idx >> 6, d = idx & 63;
        int i = n >> 8, j = (n >> 4) & 15, k = n & 15;
        float p0 = i * (1.f / 15.f) - 0.5f;
        float p1 = j * (1.f / 15.f) - 0.5f;
        float p2 = k * (1.f / 15.f) - 0.5f;
        g_pth[idx] = p0 * gthw[d * 3] + p1 * gthw[d * 3 + 1] + p2 * gthw[d * 3 + 2] + gthb[d];
        g_pph[idx] = p0 * gphw[d * 3] + p1 * gphw[d * 3 + 1] + p2 * gphw[d * 3 + 2] + gphb[d];
    }
}

// ---------------- K2: gram — ONE line per block, 64 threads ------------------
// mode 0: f_p from pth/pph (grid 768). mode 1: f from proj (grid 1536).
// Thread (v2,vp2) in an 8x8 grid computes the 2x2 sub-block of the 16x16 Gram.
__global__ __launch_bounds__(64) void k_gram(int mode) {
    __shared__ float T[2][16][68];                // [theta|phi][node][dim]
    __shared__ float ssl[48];
    int t = threadIdx.x;
    int task = blockIdx.x;
    int b = task / 768, lt = task - b * 768;
    int axis = lt >> 8, line = lt & 255;

    const float* thB; const float* phB; int stride; float* fB; float* ssB;
    if (mode) {
        thB = g_proj + b * NNODE * PROJW; phB = thB + 64; stride = PROJW;
        fB = g_f + b * NNODE * EDIM; ssB = g_ss + b * EDIM * 32;
    } else {
        thB = g_pth; phB = g_pph; stride = 64;
        fB = g_fp; ssB = g_ssfp;
    }

    if (t < 48) ssl[t] = 0.f;

    int nbse, st, c0, c1; line_decode(axis, line, nbse, st, c0, c1);

    // cooperative load: 2 tiles x 16 rows x 64 floats = 512 float4; 8 per thread
#pragma unroll
    for (int i = 0; i < 8; i++) {
        int c = t + (i << 6);                     // 0..511
        int which = c >> 8;
        int r = (c >> 4) & 15, off = c & 15;
        const float* src = (which ? phB : thB) + (nbse + r * st) * stride + off * 4;
        *(float4*)&T[which][r][off * 4] = *(const float4*)src;
    }
    __syncthreads();

    int v2 = t >> 3, vp2 = t & 7;
    const float4* t0 = (const float4*)&T[0][2 * v2][0];
    const float4* t1 = (const float4*)&T[0][2 * v2 + 1][0];
    const float4* p0 = (const float4*)&T[1][2 * vp2][0];
    const float4* p1 = (const float4*)&T[1][2 * vp2 + 1][0];
    float a00 = 0.f, a01 = 0.f, a10 = 0.f, a11 = 0.f;   // 4 independent chains
#pragma unroll
    for (int d = 0; d < 16; d++) {
        float4 x0 = t0[d], x1 = t1[d], y0 = p0[d], y1 = p1[d];
        a00 += x0.x * y0.x + x0.y * y0.y + x0.z * y0.z + x0.w * y0.w;
        a01 += x0.x * y1.x + x0.y * y1.y + x0.z * y1.z + x0.w * y1.w;
        a10 += x1.x * y0.x + x1.y * y0.y + x1.z * y0.z + x1.w * y0.w;
        a11 += x1.x * y1.x + x1.y * y1.y + x1.z * y1.z + x1.w * y1.w;
    }
    float accs[2][2] = {{a00, a01}, {a10, a11}};
#pragma unroll
    for (int iv = 0; iv < 2; iv++)
#pragma unroll
        for (int jv = 0; jv < 2; jv++) {
            int v = 2 * v2 + iv, vp = 2 * vp2 + jv;
            float a = accs[iv][jv];
            if (axis == 2 || v != vp) {
                int e = e_pos(axis, c0, c1, v, vp);
                fB[(nbse + v * st) * EDIM + e] = a;
                atomicAdd(&ssl[e], a * a);
            }
        }
    __syncthreads();
    if (t < 46) {                                 // flush line sums -> global
        float sv = ssl[t];
        if (sv != 0.f) atomicAdd(ssB + t * 32, sv);
    }
}

// ---------------- K3: proj GEMM (3xTF32 mma, 64x64 tile/block, grid 384) -----
// Also zeroes g_ss (block 0) for this round's gram atomics, and on do_fpn
// computes the normalized relu'd f_p table (grid-strided).
__global__ __launch_bounds__(256) void k_proj(int do_fpn) {
    __shared__ float Ah[32][72], Al[32][72], Bh[32][72], Bl[32][72];
    int t = threadIdx.x;
    if (blockIdx.x == 0 && t < 92) g_ss[t * 32] = 0.f;
    if (do_fpn) {
        int gtid = blockIdx.x * 256 + t, gs = gridDim.x * 256;
        for (int idx = gtid; idx < NNODE * EDIM; idx += gs) {
            int e = idx % EDIM;
            g_fpn[idx] = fmaxf(g_fp[idx] / (1e-6f + sqrtf(g_ssfp[e * 32])), 0.f);
        }
    }
    int lane = t & 31, w = t >> 5;
    int g = lane >> 2, tg = lane & 3;
    int mrow = (w & 3) << 4;          // warp m-offset within 64
    int nb = (w >> 2) << 5;           // warp n-offset within 64
    int task = blockIdx.x;
    int rowTile = task / 3;
    int rowBase = rowTile << 6, colBase = (task - rowTile * 3) << 6;
    float acc[4][4];
#pragma unroll
    for (int i = 0; i < 4; i++)
#pragma unroll
        for (int j = 0; j < 4; j++) acc[i][j] = 0.f;

    for (int k0 = 0; k0 < 128; k0 += 32) {
        __syncthreads();
#pragma unroll
        for (int it = 0; it < 2; it++) {
            int idx = t + it * 256;
            int rr = idx & 63, k4 = idx >> 6;
            float4 va = *(const float4*)(g_h + (rowBase + rr) * 128 + k0 + k4 * 4);
            float4 vb = *(const float4*)(g_Wcat + (colBase + rr) * 128 + k0 + k4 * 4);
            const float* vaf = (const float*)&va;
            const float* vbf = (const float*)&vb;
#pragma unroll
            for (int jj = 0; jj < 4; jj++) {
                float av = vaf[jj];
                float ah = __uint_as_float(__float_as_uint(av) & 0xFFFFE000u);
                Ah[k4 * 4 + jj][rr] = ah;
                Al[k4 * 4 + jj][rr] = av - ah;
                float bv = vbf[jj];
                float bh = __uint_as_float(__float_as_uint(bv) & 0xFFFFE000u);
                Bh[k4 * 4 + jj][rr] = bh;
                Bl[k4 * 4 + jj][rr] = bv - bh;
            }
        }
        __syncthreads();
#pragma unroll
        for (int ks = 0; ks < 4; ks++) {
            int kr = ks * 8;
            uint32_t ah[4], al[4];
            ah[0] = __float_as_uint(Ah[kr + tg][mrow + g]);
            ah[1] = __float_as_uint(Ah[kr + tg][mrow + g + 8]);
            ah[2] = __float_as_uint(Ah[kr + tg + 4][mrow + g]);
            ah[3] = __float_as_uint(Ah[kr + tg + 4][mrow + g + 8]);
            al[0] = __float_as_uint(Al[kr + tg][mrow + g]);
            al[1] = __float_as_uint(Al[kr + tg][mrow + g + 8]);
            al[2] = __float_as_uint(Al[kr + tg + 4][mrow + g]);
            al[3] = __float_as_uint(Al[kr + tg + 4][mrow + g + 8]);
#pragma unroll
            for (int ch = 0; ch < 4; ch++) {
                int nn = nb + ch * 8 + g;
                uint32_t bh0 = __float_as_uint(Bh[kr + tg][nn]);
                uint32_t bh1 = __float_as_uint(Bh[kr + tg + 4][nn]);
                uint32_t bl0 = __float_as_uint(Bl[kr + tg][nn]);
                uint32_t bl1 = __float_as_uint(Bl[kr + tg + 4][nn]);
                mma8(acc[ch], ah, bh0, bh1);     // hi*hi
                mma8(acc[ch], ah, bl0, bl1);     // hi*lo
                mma8(acc[ch], al, bh0, bh1);     // lo*hi
            }
        }
    }
#pragma unroll
    for (int ch = 0; ch < 4; ch++) {
        int col = colBase + nb + ch * 8 + 2 * tg;
        int row = rowBase + mrow + g;
        g_proj[row * PROJW + col]           = acc[ch][0] + g_bcat[col];
        g_proj[row * PROJW + col + 1]       = acc[ch][1] + g_bcat[col + 1];
        g_proj[(row + 8) * PROJW + col]     = acc[ch][2] + g_bcat[col];
        g_proj[(row + 8) * PROJW + col + 1] = acc[ch][3] + g_bcat[col + 1];
    }
}

// ---------------- K4: softmax + aggregate (grid 1536, 1 line each) -----------
__global__ __launch_bounds__(256) void k_agg() {
    __shared__ float Gs[16][68];
    __shared__ float fs[16][48];
    __shared__ float nrm2[92];
    int t = threadIdx.x;
    int task = blockIdx.x;
    int b = task / 768, lt = task - b * 768;
    int axis = lt >> 8, line = lt & 255;
    int nb_, st, c0, c1; line_decode(axis, line, nb_, st, c0, c1);

    if (t < 92) nrm2[t] = 1.f / (1e-6f + sqrtf(g_ss[t * 32]));

    int r = t >> 4, c = t & 15;
    // loads into registers (no smem dependency yet)
    float4 gv = *(const float4*)(g_proj + (b * NNODE + nb_ + r * st) * PROJW + 128 + c * 4);
    float fv[3], qv[3]; int lnd[3], le[3];
#pragma unroll
    for (int ii = 0; ii < 3; ii++) {
        int l = t + ii * 256; lnd[ii] = l / 48; le[ii] = l - lnd[ii] * 48;
        if (le[ii] < 46) {
            int n = nb_ + lnd[ii] * st;
            fv[ii] = g_f[(b * NNODE + n) * EDIM + le[ii]];
            qv[ii] = g_fpn[n * EDIM + le[ii]];
        }
    }
    __syncthreads();                              // nrm2 visible
    *(float4*)&Gs[r][c * 4] = gv;
#pragma unroll
    for (int ii = 0; ii < 3; ii++)
        fs[lnd[ii]][le[ii]] = (le[ii] < 46)
            ? fv[ii] * nrm2[b * 46 + le[ii]] + qv[ii] : -1e30f;
    __syncthreads();

    int ty = r, tx = c;
    float a0 = fs[ty][tx], a1 = fs[ty][tx + 16], a2 = fs[ty][tx + 32];
    float m = fmaxf(a0, fmaxf(a1, a2));
#pragma unroll
    for (int o = 8; o; o >>= 1) m = fmaxf(m, __shfl_xor_sync(0xffffffffu, m, o));
    float e0 = expf(a0 - m), e1 = expf(a1 - m), e2 = expf(a2 - m);
    float z = e0 + e1 + e2;
#pragma unroll
    for (int o = 8; o; o >>= 1) z += __shfl_xor_sync(0xffffffffu, z, o);
    float invZ = 1.f / z;
    fs[ty][tx] = e0; fs[ty][tx + 16] = e1; fs[ty][tx + 32] = e2;
    __syncwarp();

    float4 acc = {0.f, 0.f, 0.f, 0.f};
#pragma unroll
    for (int vp = 0; vp < 16; vp++) {
        float w;
        if (axis == 2)      w = fs[ty][c0 + c1 + vp];
        else if (vp == ty)  w = 0.f;
        else if (axis == 0) w = fs[ty][vp < ty ? vp : vp + 30];
        else                w = fs[ty][c0 + (vp < ty ? vp : vp + 15)];
        float4 gg = *(const float4*)&Gs[vp][tx * 4];
        acc.x += w * gg.x; acc.y += w * gg.y; acc.z += w * gg.z; acc.w += w * gg.w;
    }
    acc.x *= invZ; acc.y *= invZ; acc.z *= invZ; acc.w *= invZ;
    int n = nb_ + ty * st;
    *(float4*)&g_y[axis][(b * NNODE + n) * 64 + tx * 4] = acc;
}

// ---------------- K5: residual GEMM (grid 256, 64x64 tile) -------------------
__global__ __launch_bounds__(256) void k_resid(const float* __restrict__ rw,
                                               const float* __restrict__ rb,
                                               float* __restrict__ outp, int last) {
    __shared__ float A[32][68], B[32][68];
    int task = blockIdx.x;
    int rowBase = (task >> 1) << 6, colBase = (task & 1) << 6;
    int t = threadIdx.x, tx = t & 15, ty = t >> 4;
    const int AX = BCNT * NNODE * 64;
    float acc[4][4] = {};
    for (int k0 = 0; k0 < 64; k0 += 32) {
#pragma unroll
        for (int it = 0; it < 2; it++) {
            int idx = t + it * 256;
            int r = idx & 63, k4 = idx >> 6;
            const float* yb = &g_y[0][(rowBase + r) * 64 + k0 + k4 * 4];
            float4 v0 = *(const float4*)yb;
            float4 v1 = *(const float4*)(yb + AX);
            float4 v2 = *(const float4*)(yb + 2 * AX);
            A[k4 * 4 + 0][r] = v0.x + v1.x + v2.x;
            A[k4 * 4 + 1][r] = v0.y + v1.y + v2.y;
            A[k4 * 4 + 2][r] = v0.z + v1.z + v2.z;
            A[k4 * 4 + 3][r] = v0.w + v1.w + v2.w;
            float4 w = *(const float4*)(rw + (colBase + r) * 64 + k0 + k4 * 4);
            B[k4 * 4 + 0][r] = w.x; B[k4 * 4 + 1][r] = w.y;
            B[k4 * 4 + 2][r] = w.z; B[k4 * 4 + 3][r] = w.w;
        }
        __syncthreads();
#pragma unroll
        for (int kk = 0; kk < 32; kk++) {
            float4 a = *(const float4*)&A[kk][ty * 4];
            float4 b = *(const float4*)&B[kk][tx * 4];
            float av[4] = {a.x, a.y, a.z, a.w};
            float bv[4] = {b.x, b.y, b.z, b.w};
#pragma unroll
            for (int i = 0; i < 4; i++)
#pragma unroll
                for (int j = 0; j < 4; j++) acc[i][j] += av[i] * bv[j];
        }
        __syncthreads();
    }
#pragma unroll
    for (int i = 0; i < 4; i++) {
        int row = rowBase + ty * 4 + i;
#pragma unroll
        for (int j = 0; j < 4; j++) {
            int c = colBase + tx * 4 + j;
            float val = acc[i][j] + rb[c] + g_h[row * 128 + c];
            if (last) {
                int b = row >> 12, n = row & 4095;
                outp[(((b << 7) + c) << 12) + n] = val;
            } else {
                g_h[row * 128 + c] = val;
            }
        }
    }
}

// ---------------------------------------------------------------------------
extern "C" void kernel_launch(void* const* d_in, const int* in_sizes, int n_in,
                              void* d_out, int out_size) {
    const float* x    = (const float*)d_in[0];
    const float* G_w  = (const float*)d_in[1];
    const float* G_b  = (const float*)d_in[2];
    const float* th_w = (const float*)d_in[3];
    const float* th_b = (const float*)d_in[4];
    const float* ph_w = (const float*)d_in[5];
    const float* ph_b = (const float*)d_in[6];
    const float* r_w  = (const float*)d_in[7];
    const float* r_b  = (const float*)d_in[8];
    const float* gt_w = (const float*)d_in[9];
    const float* gt_b = (const float*)d_in[10];
    const float* gp_w = (const float*)d_in[11];
    const float* gp_b = (const float*)d_in[12];
    float* out = (float*)d_out;

    k_prep<<<512, 256>>>(x, G_w, G_b, th_w, th_b, ph_w, ph_b,
                         gt_w, gt_b, gp_w, gp_b);
    k_gram<<<768, 64>>>(0);                        // f_p lines (1 line/block)

    for (int r = 0; r < 3; r++) {
        k_proj<<<384, 256>>>(r == 0 ? 1 : 0);      // + zero g_ss, + FPN on r0
        k_gram<<<1536, 64>>>(1);                   // f lines (1 line/block)
        k_agg<<<1536, 256>>>();
        k_resid<<<256, 256>>>(r_w, r_b, out, r == 2);
    }
}